// round 11
// baseline (speedup 1.0000x reference)
#include <cuda_runtime.h>
#include <math.h>

#define BTT 192            // B*T
#define NNODE 207
#define DMODEL 256
#define NHEADS 8
#define DHEAD 32
#define MTOT (BTT * NNODE) // 39744

// weight split offsets (elements) inside g_Whi / g_Wlo
#define OFF_WQ 0
#define OFF_WK 65536
#define OFF_WV 131072
#define OFF_WP 196608
#define OFF_WG 262144
#define W_TOTAL 393216

// ---------------- scratch -------------------------------------------------
__device__ float g_Q [MTOT * DMODEL];
__device__ float g_K [MTOT * DMODEL];
__device__ float g_V [MTOT * DMODEL];
__device__ float g_Zi[MTOT * DMODEL];
__device__ float g_Zj[MTOT * DMODEL];
__device__ float g_Zc[MTOT * DMODEL];
__device__ unsigned g_Whi[W_TOTAL];
__device__ unsigned g_Wlo[W_TOTAL];

// ---------------- tf32 helpers ---------------------------------------------
__device__ __forceinline__ unsigned f2tf32(float x) {
    unsigned r;
    asm("cvt.rna.tf32.f32 %0, %1;" : "=r"(r) : "f"(x));
    return r;
}
__device__ __forceinline__ uint2 split2(float v) {
    unsigned h = f2tf32(v);
    return make_uint2(h, f2tf32(__fsub_rn(v, __uint_as_float(h))));
}
__device__ __forceinline__ void mma_tf32(float4& c, const unsigned a[4], const unsigned b[2]) {
    asm volatile(
        "mma.sync.aligned.m16n8k8.row.col.f32.tf32.tf32.f32 "
        "{%0,%1,%2,%3}, {%4,%5,%6,%7}, {%8,%9}, {%0,%1,%2,%3};"
        : "+f"(c.x), "+f"(c.y), "+f"(c.z), "+f"(c.w)
        : "r"(a[0]), "r"(a[1]), "r"(a[2]), "r"(a[3]), "r"(b[0]), "r"(b[1]));
}

// ---------------- weight pre-split ------------------------------------------
__global__ __launch_bounds__(256)
void split_weights(const float* __restrict__ Wq, const float* __restrict__ Wk,
                   const float* __restrict__ Wv, const float* __restrict__ Wp,
                   const float* __restrict__ Wg)
{
    int i = blockIdx.x * 256 + threadIdx.x;
    if (i >= W_TOTAL) return;
    const float* src; int off;
    if      (i < OFF_WK) { src = Wq; off = OFF_WQ; }
    else if (i < OFF_WV) { src = Wk; off = OFF_WK; }
    else if (i < OFF_WP) { src = Wv; off = OFF_WV; }
    else if (i < OFF_WG) { src = Wp; off = OFF_WP; }
    else                 { src = Wg; off = OFF_WG; }
    float v = src[i - off];
    unsigned h = f2tf32(v);
    g_Whi[i] = h;
    g_Wlo[i] = f2tf32(__fsub_rn(v, __uint_as_float(h)));
}

// ---------------- tensor-core GEMM (3xTF32) — round-8 shape, 2 CTAs/SM -------
// 128x128 CTA tile, BK=32. 8 warps (2x4), each warp 64x32 via 4x4 m16n8k8.
// __launch_bounds__(256, 2) caps regs at 128 so two CTAs share an SM; the
// register overflow (staging arrays) spills to local in the prefetch shadow.
#define GBM 128
#define GBN 128
#define GBK 32
#define AS2_LD 36          // uint2 stride
#define BS_LD 136          // u32 stride
#define GEMM_SMEM (GBM * AS2_LD * 8 + 2 * GBK * BS_LD * 4)   // 71680 B

template<int MODE>
__global__ __launch_bounds__(256, 2)
void gemm_tc(const float* __restrict__ A0, const float* __restrict__ A1,
             const unsigned* __restrict__ BhiBase, const unsigned* __restrict__ BloBase,
             const float* __restrict__ b0, const float* __restrict__ b1,
             const float* __restrict__ b2,
             const float* __restrict__ Zi, const float* __restrict__ Zj,
             float* __restrict__ C0, float* __restrict__ C1, float* __restrict__ C2,
             int M, int K)
{
    extern __shared__ char sm[];
    uint2*    As2 = (uint2*)sm;                               // [128][36]
    unsigned* BsH = (unsigned*)(sm + GBM * AS2_LD * 8);       // [32][136]
    unsigned* BsL = BsH + GBK * BS_LD;

    const int N = DMODEL;

    const int sel = (MODE == 2) ? (blockIdx.y >> 1) : 0;
    const int bn  = (MODE == 2) ? (blockIdx.y & 1) * GBN : blockIdx.y * GBN;
    const unsigned* Bhi = BhiBase + (MODE == 2 ? sel * 65536 : 0);
    const unsigned* Blo = BloBase + (MODE == 2 ? sel * 65536 : 0);
    const float* bias = (MODE == 2) ? (sel == 0 ? b0 : (sel == 1 ? b1 : b2)) : b0;
    float* C          = (MODE == 2) ? (sel == 0 ? C0 : (sel == 1 ? C1 : C2)) : C0;

    const int bm = blockIdx.x * GBM;
    const int tid  = threadIdx.x;
    const int wid  = tid >> 5;
    const int lane = tid & 31;
    const int rb = (wid >> 2) * 64;
    const int cb = (wid & 3) * 32;
    const int g   = lane >> 2;
    const int tig = lane & 3;

    float4 apf[4];
    uint4  bpfH[4], bpfL[4];

    float4 acc[4][4];
#pragma unroll
    for (int mt = 0; mt < 4; mt++)
#pragma unroll
        for (int nt = 0; nt < 4; nt++) acc[mt][nt] = make_float4(0.f, 0.f, 0.f, 0.f);

    auto load_tile = [&](int kt) {
#pragma unroll
        for (int i = 0; i < 4; i++) {
            int idx = tid + i * 256;
            int row = idx >> 3;
            int c4  = idx & 7;
            int gm  = bm + row;
            int gk  = kt + c4 * 4;
            float4 v = make_float4(0.f, 0.f, 0.f, 0.f);
            if (gm < M) {
                if (MODE == 1) {
                    const float* Ap = (gk < DMODEL) ? A0 : A1;
                    int col = gk & (DMODEL - 1);
                    v = *(const float4*)&Ap[(size_t)gm * DMODEL + col];
                } else {
                    v = *(const float4*)&A0[(size_t)gm * K + gk];
                }
            }
            apf[i] = v;
        }
#pragma unroll
        for (int i = 0; i < 4; i++) {
            int idx = tid + i * 256;
            int row = idx >> 5;
            int c4  = idx & 31;
            size_t gi = (size_t)(kt + row) * N + bn + c4 * 4;
            bpfH[i] = *(const uint4*)&Bhi[gi];
            bpfL[i] = *(const uint4*)&Blo[gi];
        }
    };
    auto store_tile = [&]() {
#pragma unroll
        for (int i = 0; i < 4; i++) {
            int idx = tid + i * 256;
            int row = idx >> 3;
            int c4  = idx & 7;
            float4 v = apf[i];
            unsigned h0 = f2tf32(v.x), h1 = f2tf32(v.y), h2 = f2tf32(v.z), h3 = f2tf32(v.w);
            unsigned l0 = f2tf32(__fsub_rn(v.x, __uint_as_float(h0)));
            unsigned l1 = f2tf32(__fsub_rn(v.y, __uint_as_float(h1)));
            unsigned l2 = f2tf32(__fsub_rn(v.z, __uint_as_float(h2)));
            unsigned l3 = f2tf32(__fsub_rn(v.w, __uint_as_float(h3)));
            uint4* p = (uint4*)&As2[row * AS2_LD + c4 * 4];
            p[0] = make_uint4(h0, l0, h1, l1);
            p[1] = make_uint4(h2, l2, h3, l3);
        }
#pragma unroll
        for (int i = 0; i < 4; i++) {
            int idx = tid + i * 256;
            int row = idx >> 5;
            int c4  = idx & 31;
            *(uint4*)&BsH[row * BS_LD + c4 * 4] = bpfH[i];
            *(uint4*)&BsL[row * BS_LD + c4 * 4] = bpfL[i];
        }
    };

    load_tile(0);
    store_tile();
    __syncthreads();

    for (int kt = 0; kt < K; kt += GBK) {
        const bool has_next = (kt + GBK) < K;
        if (has_next) load_tile(kt + GBK);

#pragma unroll
        for (int s = 0; s < 4; s++) {
            const int k0 = s * 8;
            unsigned ahi[4][4], alo[4][4];
#pragma unroll
            for (int mt = 0; mt < 4; mt++) {
                const int r0 = (rb + mt * 16 + g) * AS2_LD + k0;
                uint2 v0 = As2[r0 + tig];
                uint2 v1 = As2[r0 + 8 * AS2_LD + tig];
                uint2 v2 = As2[r0 + tig + 4];
                uint2 v3 = As2[r0 + 8 * AS2_LD + tig + 4];
                ahi[mt][0] = v0.x; alo[mt][0] = v0.y;
                ahi[mt][1] = v1.x; alo[mt][1] = v1.y;
                ahi[mt][2] = v2.x; alo[mt][2] = v2.y;
                ahi[mt][3] = v3.x; alo[mt][3] = v3.y;
            }
            unsigned bhi[4][2], blo[4][2];
#pragma unroll
            for (int nt = 0; nt < 4; nt++) {
                const int c0 = cb + nt * 8 + g;
                bhi[nt][0] = BsH[(k0 + tig) * BS_LD + c0];
                bhi[nt][1] = BsH[(k0 + tig + 4) * BS_LD + c0];
                blo[nt][0] = BsL[(k0 + tig) * BS_LD + c0];
                blo[nt][1] = BsL[(k0 + tig + 4) * BS_LD + c0];
            }
#pragma unroll
            for (int mt = 0; mt < 4; mt++)
#pragma unroll
                for (int nt = 0; nt < 4; nt++) {
                    mma_tf32(acc[mt][nt], ahi[mt], bhi[nt]);
                    mma_tf32(acc[mt][nt], ahi[mt], blo[nt]);
                    mma_tf32(acc[mt][nt], alo[mt], bhi[nt]);
                }
        }

        __syncthreads();
        if (has_next) {
            store_tile();
            __syncthreads();
        }
    }

#pragma unroll
    for (int nt = 0; nt < 4; nt++) {
        const int col = bn + cb + nt * 8 + tig * 2;
        const float bv0 = bias[col];
        const float bv1 = bias[col + 1];
#pragma unroll
        for (int mt = 0; mt < 4; mt++) {
            const int row0 = bm + rb + mt * 16 + g;
            const int row1 = row0 + 8;
            const float4 a = acc[mt][nt];
            if (MODE != 1) {
                if (row0 < M) {
                    float2 o = make_float2(a.x + bv0, a.y + bv1);
                    *(float2*)&C[(size_t)row0 * N + col] = o;
                }
                if (row1 < M) {
                    float2 o = make_float2(a.z + bv0, a.w + bv1);
                    *(float2*)&C[(size_t)row1 * N + col] = o;
                }
            } else {
                if (row0 < M) {
                    size_t base = (size_t)row0 * N + col;
                    float2 zi = *(const float2*)&Zi[base];
                    float2 zj = *(const float2*)&Zj[base];
                    float g0 = 1.f / (1.f + __expf(-(a.x + bv0)));
                    float g1 = 1.f / (1.f + __expf(-(a.y + bv1)));
                    float2 o = make_float2(g0 * zi.x + (1.f - g0) * zj.x,
                                           g1 * zi.y + (1.f - g1) * zj.y);
                    *(float2*)&C[base] = o;
                }
                if (row1 < M) {
                    size_t base = (size_t)row1 * N + col;
                    float2 zi = *(const float2*)&Zi[base];
                    float2 zj = *(const float2*)&Zj[base];
                    float g0 = 1.f / (1.f + __expf(-(a.z + bv0)));
                    float g1 = 1.f / (1.f + __expf(-(a.w + bv1)));
                    float2 o = make_float2(g0 * zi.x + (1.f - g0) * zj.x,
                                           g1 * zi.y + (1.f - g1) * zj.y);
                    *(float2*)&C[base] = o;
                }
            }
        }
    }
}

// ---------------- MMA attention (round-8, unchanged) -------------------------
#define KV_LD 36    // uint2 stride
#define P_LD 40     // f32 stride
#define ATTN_SMEM (224*KV_LD*8*2 + 8*32*P_LD*4*2)   // 210944 B

__global__ __launch_bounds__(256)
void attn_mma(const float* __restrict__ Q, const float* __restrict__ K,
              const float* __restrict__ V,
              float* __restrict__ Zi, float* __restrict__ Zj)
{
    extern __shared__ char smraw[];
    uint2* Ks = (uint2*)smraw;               // [224][36]
    uint2* Vs = Ks + 224 * KV_LD;            // [224][36]
    float* Pw  = (float*)(Vs + 224 * KV_LD); // [8][32*40]
    float* Piw = Pw + 8 * 32 * P_LD;         // [8][32*40]

    const int bt = blockIdx.x >> 3;
    const int h  = blockIdx.x & 7;
    const size_t base = ((size_t)bt * NNODE) * DMODEL + h * DHEAD;
    const int tid = threadIdx.x;
    const int w = tid >> 5, lane = tid & 31;
    const int g = lane >> 2, tig = lane & 3;

    for (int idx = tid; idx < 224 * 32; idx += 256) {
        int row = idx >> 5, col = idx & 31;
        float kv = 0.f, vv = 0.f;
        if (row < NNODE) {
            kv = K[base + (size_t)row * DMODEL + col];
            vv = V[base + (size_t)row * DMODEL + col];
        }
        Ks[row * KV_LD + col] = split2(kv);
        Vs[row * KV_LD + col] = split2(vv);
    }

    float* myP  = Pw  + w * (32 * P_LD);
    float* myPi = Piw + w * (32 * P_LD);
    for (int i = lane; i < 32 * P_LD; i += 32) myPi[i] = 0.f;

    const float scale = 0.1767766952966369f; // 1/sqrt(32)
    unsigned qh[2][4][4], ql[2][4][4];
#pragma unroll
    for (int mt = 0; mt < 2; mt++)
#pragma unroll
        for (int ks = 0; ks < 4; ks++) {
            int r0 = mt * 16 + g, r1 = r0 + 8;
            int n0 = w + 8 * r0; if (n0 > 206) n0 = 206;
            int n1 = w + 8 * r1; if (n1 > 206) n1 = 206;
            int k0 = 8 * ks + tig;
            float a0 = Q[base + (size_t)n0 * DMODEL + k0] * scale;
            float a1 = Q[base + (size_t)n1 * DMODEL + k0] * scale;
            float a2 = Q[base + (size_t)n0 * DMODEL + k0 + 4] * scale;
            float a3 = Q[base + (size_t)n1 * DMODEL + k0 + 4] * scale;
            uint2 s0 = split2(a0), s1 = split2(a1), s2 = split2(a2), s3 = split2(a3);
            qh[mt][ks][0] = s0.x; ql[mt][ks][0] = s0.y;
            qh[mt][ks][1] = s1.x; ql[mt][ks][1] = s1.y;
            qh[mt][ks][2] = s2.x; ql[mt][ks][2] = s2.y;
            qh[mt][ks][3] = s3.x; ql[mt][ks][3] = s3.y;
        }
    __syncthreads();

    float4 zall[2][4], zint[2][4];
#pragma unroll
    for (int mt = 0; mt < 2; mt++)
#pragma unroll
        for (int nt = 0; nt < 4; nt++) {
            zall[mt][nt] = make_float4(0.f, 0.f, 0.f, 0.f);
            zint[mt][nt] = make_float4(0.f, 0.f, 0.f, 0.f);
        }
    float sa[4] = {0.f, 0.f, 0.f, 0.f};
    float si[4] = {0.f, 0.f, 0.f, 0.f};
    const bool isHolder = (tig == (w >> 1));
    const int wodd = w & 1;

    for (int ct = 0; ct < 7; ct++) {
        const int mbase = 32 * ct;

        float4 sacc[2][4];
#pragma unroll
        for (int mt = 0; mt < 2; mt++)
#pragma unroll
            for (int nt = 0; nt < 4; nt++) sacc[mt][nt] = make_float4(0.f, 0.f, 0.f, 0.f);

#pragma unroll
        for (int ks = 0; ks < 4; ks++)
#pragma unroll
            for (int nt = 0; nt < 4; nt++) {
                int mrow = (mbase + 8 * nt + g) * KV_LD;
                uint2 kb0 = Ks[mrow + 8 * ks + tig];
                uint2 kb1 = Ks[mrow + 8 * ks + tig + 4];
                unsigned bh[2] = {kb0.x, kb1.x};
                unsigned bl[2] = {kb0.y, kb1.y};
#pragma unroll
                for (int mt = 0; mt < 2; mt++) {
                    mma_tf32(sacc[mt][nt], qh[mt][ks], bh);
                    mma_tf32(sacc[mt][nt], qh[mt][ks], bl);
                    mma_tf32(sacc[mt][nt], ql[mt][ks], bh);
                }
            }

#pragma unroll
        for (int mt = 0; mt < 2; mt++)
#pragma unroll
            for (int nt = 0; nt < 4; nt++) {
                float4 c = sacc[mt][nt];
                int m0 = mbase + 8 * nt + 2 * tig, m1 = m0 + 1;
                int r0 = mt * 16 + g, r1 = r0 + 8;
                int n0 = w + 8 * r0, n1 = w + 8 * r1;
                c.x = (m0 <= 206 && m0 != n0) ? __expf(c.x) : 0.f;
                c.y = (m1 <= 206 && m1 != n0) ? __expf(c.y) : 0.f;
                c.z = (m0 <= 206 && m0 != n1) ? __expf(c.z) : 0.f;
                c.w = (m1 <= 206 && m1 != n1) ? __expf(c.w) : 0.f;
                sa[mt * 2 + 0] += c.x + c.y;
                sa[mt * 2 + 1] += c.z + c.w;
                if (isHolder) {
                    float v0 = wodd ? c.y : c.x;
                    float v1 = wodd ? c.w : c.z;
                    si[mt * 2 + 0] += v0;
                    si[mt * 2 + 1] += v1;
                    myPi[r0 * P_LD + 4 * ct + nt] = v0;
                    myPi[r1 * P_LD + 4 * ct + nt] = v1;
                }
                *(float2*)&myP[r0 * P_LD + 8 * nt + 2 * tig] = make_float2(c.x, c.y);
                *(float2*)&myP[r1 * P_LD + 8 * nt + 2 * tig] = make_float2(c.z, c.w);
            }
        __syncwarp();

#pragma unroll
        for (int ks = 0; ks < 4; ks++) {
            unsigned ah[2][4], al[2][4];
#pragma unroll
            for (int mt = 0; mt < 2; mt++) {
                int r0 = (mt * 16 + g) * P_LD, r1 = (mt * 16 + g + 8) * P_LD;
                float p0 = myP[r0 + 8 * ks + tig];
                float p1 = myP[r1 + 8 * ks + tig];
                float p2 = myP[r0 + 8 * ks + tig + 4];
                float p3 = myP[r1 + 8 * ks + tig + 4];
                uint2 s0 = split2(p0), s1 = split2(p1), s2 = split2(p2), s3 = split2(p3);
                ah[mt][0] = s0.x; al[mt][0] = s0.y;
                ah[mt][1] = s1.x; al[mt][1] = s1.y;
                ah[mt][2] = s2.x; al[mt][2] = s2.y;
                ah[mt][3] = s3.x; al[mt][3] = s3.y;
            }
#pragma unroll
            for (int nt = 0; nt < 4; nt++) {
                int kr = mbase + 8 * ks + tig;
                uint2 vb0 = Vs[kr * KV_LD + 8 * nt + g];
                uint2 vb1 = Vs[(kr + 4) * KV_LD + 8 * nt + g];
                unsigned bh[2] = {vb0.x, vb1.x};
                unsigned bl[2] = {vb0.y, vb1.y};
#pragma unroll
                for (int mt = 0; mt < 2; mt++) {
                    mma_tf32(zall[mt][nt], ah[mt], bh);
                    mma_tf32(zall[mt][nt], ah[mt], bl);
                    mma_tf32(zall[mt][nt], al[mt], bh);
                }
            }
        }
        __syncwarp();
    }

#pragma unroll
    for (int ks = 0; ks < 4; ks++) {
        unsigned ah[2][4], al[2][4];
#pragma unroll
        for (int mt = 0; mt < 2; mt++) {
            int r0 = (mt * 16 + g) * P_LD, r1 = (mt * 16 + g + 8) * P_LD;
            float p0 = myPi[r0 + 8 * ks + tig];
            float p1 = myPi[r1 + 8 * ks + tig];
            float p2 = myPi[r0 + 8 * ks + tig + 4];
            float p3 = myPi[r1 + 8 * ks + tig + 4];
            uint2 s0 = split2(p0), s1 = split2(p1), s2 = split2(p2), s3 = split2(p3);
            ah[mt][0] = s0.x; al[mt][0] = s0.y;
            ah[mt][1] = s1.x; al[mt][1] = s1.y;
            ah[mt][2] = s2.x; al[mt][2] = s2.y;
            ah[mt][3] = s3.x; al[mt][3] = s3.y;
        }
#pragma unroll
        for (int nt = 0; nt < 4; nt++) {
            int k0 = 8 * ks + tig;
            int mk0 = w + 8 * k0;       if (mk0 > 223) mk0 = 223;
            int mk1 = w + 8 * (k0 + 4); if (mk1 > 223) mk1 = 223;
            uint2 vb0 = Vs[mk0 * KV_LD + 8 * nt + g];
            uint2 vb1 = Vs[mk1 * KV_LD + 8 * nt + g];
            unsigned bh[2] = {vb0.x, vb1.x};
            unsigned bl[2] = {vb0.y, vb1.y};
#pragma unroll
            for (int mt = 0; mt < 2; mt++) {
                mma_tf32(zint[mt][nt], ah[mt], bh);
                mma_tf32(zint[mt][nt], ah[mt], bl);
                mma_tf32(zint[mt][nt], al[mt], bh);
            }
        }
    }

    float ri[4], rj[4];
#pragma unroll
    for (int i = 0; i < 4; i++) {
        float a = sa[i], s = si[i];
        a += __shfl_xor_sync(0xffffffffu, a, 1);
        a += __shfl_xor_sync(0xffffffffu, a, 2);
        s += __shfl_xor_sync(0xffffffffu, s, 1);
        s += __shfl_xor_sync(0xffffffffu, s, 2);
        ri[i] = 1.f / s;
        rj[i] = 1.f / (a - s);
    }

    __syncwarp();
#pragma unroll
    for (int mt = 0; mt < 2; mt++)
#pragma unroll
        for (int nt = 0; nt < 4; nt++) {
            int r0 = mt * 16 + g, r1 = r0 + 8;
            float4 za = zall[mt][nt], zi4 = zint[mt][nt];
            float ri0 = ri[mt * 2], ri1 = ri[mt * 2 + 1];
            float rj0 = rj[mt * 2], rj1 = rj[mt * 2 + 1];
            *(float2*)&myP [r0 * P_LD + 8 * nt + 2 * tig] = make_float2(zi4.x * ri0, zi4.y * ri0);
            *(float2*)&myP [r1 * P_LD + 8 * nt + 2 * tig] = make_float2(zi4.z * ri1, zi4.w * ri1);
            *(float2*)&myPi[r0 * P_LD + 8 * nt + 2 * tig] = make_float2((za.x - zi4.x) * rj0, (za.y - zi4.y) * rj0);
            *(float2*)&myPi[r1 * P_LD + 8 * nt + 2 * tig] = make_float2((za.z - zi4.z) * rj1, (za.w - zi4.w) * rj1);
        }
    __syncwarp();
#pragma unroll 4
    for (int rr = 0; rr < 32; rr++) {
        int n = w + 8 * rr;
        if (n < NNODE) {
            Zi[base + (size_t)n * DMODEL + lane] = myP [rr * P_LD + lane];
            Zj[base + (size_t)n * DMODEL + lane] = myPi[rr * P_LD + lane];
        }
    }
}

// ---------------- launch --------------------------------------------------
extern "C" void kernel_launch(void* const* d_in, const int* in_sizes, int n_in,
                              void* d_out, int out_size)
{
    const float* x  = (const float*)d_in[0];
    const float* Wq = (const float*)d_in[1];
    const float* bq = (const float*)d_in[2];
    const float* Wk = (const float*)d_in[3];
    const float* bk = (const float*)d_in[4];
    const float* Wv = (const float*)d_in[5];
    const float* bv = (const float*)d_in[6];
    const float* Wg = (const float*)d_in[7];
    const float* bg = (const float*)d_in[8];
    const float* Wp = (const float*)d_in[9];
    const float* bp = (const float*)d_in[10];
    float* out = (float*)d_out;

    float *Q, *Kp, *Vp, *Zi, *Zj, *Zc;
    unsigned *Whi, *Wlo;
    cudaGetSymbolAddress((void**)&Q,  g_Q);
    cudaGetSymbolAddress((void**)&Kp, g_K);
    cudaGetSymbolAddress((void**)&Vp, g_V);
    cudaGetSymbolAddress((void**)&Zi, g_Zi);
    cudaGetSymbolAddress((void**)&Zj, g_Zj);
    cudaGetSymbolAddress((void**)&Zc, g_Zc);
    cudaGetSymbolAddress((void**)&Whi, g_Whi);
    cudaGetSymbolAddress((void**)&Wlo, g_Wlo);

    cudaFuncSetAttribute(gemm_tc<0>, cudaFuncAttributeMaxDynamicSharedMemorySize, GEMM_SMEM);
    cudaFuncSetAttribute(gemm_tc<1>, cudaFuncAttributeMaxDynamicSharedMemorySize, GEMM_SMEM);
    cudaFuncSetAttribute(gemm_tc<2>, cudaFuncAttributeMaxDynamicSharedMemorySize, GEMM_SMEM);
    cudaFuncSetAttribute(attn_mma,   cudaFuncAttributeMaxDynamicSharedMemorySize, ATTN_SMEM);

    const int mblocks = (MTOT + GBM - 1) / GBM;   // 311

    split_weights<<<(W_TOTAL + 255) / 256, 256>>>(Wq, Wk, Wv, Wp, Wg);

    gemm_tc<2><<<dim3(mblocks, 6), 256, GEMM_SMEM>>>(
        x, nullptr, Whi + OFF_WQ, Wlo + OFF_WQ, bq, bk, bv,
        nullptr, nullptr, Q, Kp, Vp, MTOT, DMODEL);

    attn_mma<<<BTT * NHEADS, 256, ATTN_SMEM>>>(Q, Kp, Vp, Zi, Zj);

    gemm_tc<1><<<dim3(mblocks, 2), 256, GEMM_SMEM>>>(
        Zi, Zj, Whi + OFF_WG, Wlo + OFF_WG, bg, nullptr, nullptr,
        Zi, Zj, Zc, nullptr, nullptr, MTOT, 2 * DMODEL);

    gemm_tc<0><<<dim3(mblocks, 2), 256, GEMM_SMEM>>>(
        Zc, nullptr, Whi + OFF_WP, Wlo + OFF_WP, bp, nullptr, nullptr,
        nullptr, nullptr, out, nullptr, nullptr, MTOT, DMODEL);
}

// round 13
// speedup vs baseline: 1.1203x; 1.1203x over previous
#include <cuda_runtime.h>
#include <math.h>

#define BTT 192            // B*T
#define NNODE 207
#define DMODEL 256
#define NHEADS 8
#define DHEAD 32
#define MTOT (BTT * NNODE) // 39744

// weight split offsets (elements) inside g_Whi / g_Wlo
#define OFF_WQ 0
#define OFF_WK 65536
#define OFF_WV 131072
#define OFF_WP 196608
#define OFF_WG 262144
#define W_TOTAL 393216

// ---------------- scratch -------------------------------------------------
__device__ float g_Q [MTOT * DMODEL];
__device__ float g_K [MTOT * DMODEL];
__device__ float g_V [MTOT * DMODEL];
__device__ float g_Zi[MTOT * DMODEL];
__device__ float g_Zj[MTOT * DMODEL];
__device__ float g_Zc[MTOT * DMODEL];
__device__ unsigned g_Whi[W_TOTAL];
__device__ unsigned g_Wlo[W_TOTAL];

// ---------------- tf32 helpers ---------------------------------------------
__device__ __forceinline__ unsigned f2tf32(float x) {
    unsigned r;
    asm("cvt.rna.tf32.f32 %0, %1;" : "=r"(r) : "f"(x));
    return r;
}
__device__ __forceinline__ uint2 split2(float v) {
    unsigned h = f2tf32(v);
    return make_uint2(h, f2tf32(__fsub_rn(v, __uint_as_float(h))));
}
__device__ __forceinline__ void mma_tf32(float4& c, const unsigned a[4], const unsigned b[2]) {
    asm volatile(
        "mma.sync.aligned.m16n8k8.row.col.f32.tf32.tf32.f32 "
        "{%0,%1,%2,%3}, {%4,%5,%6,%7}, {%8,%9}, {%0,%1,%2,%3};"
        : "+f"(c.x), "+f"(c.y), "+f"(c.z), "+f"(c.w)
        : "r"(a[0]), "r"(a[1]), "r"(a[2]), "r"(a[3]), "r"(b[0]), "r"(b[1]));
}
__device__ __forceinline__ void cp16(void* s, const void* g) {
    unsigned sa = (unsigned)__cvta_generic_to_shared(s);
    asm volatile("cp.async.cg.shared.global [%0], [%1], 16;\n" :: "r"(sa), "l"(g));
}
template<int N_> __device__ __forceinline__ void cp_wait() {
    asm volatile("cp.async.wait_group %0;\n" :: "n"(N_));
}
__device__ __forceinline__ void cp_commit() {
    asm volatile("cp.async.commit_group;\n");
}

// ---------------- weight pre-split ------------------------------------------
__global__ __launch_bounds__(256)
void split_weights(const float* __restrict__ Wq, const float* __restrict__ Wk,
                   const float* __restrict__ Wv, const float* __restrict__ Wp,
                   const float* __restrict__ Wg)
{
    int i = blockIdx.x * 256 + threadIdx.x;
    if (i >= W_TOTAL) return;
    const float* src; int off;
    if      (i < OFF_WK) { src = Wq; off = OFF_WQ; }
    else if (i < OFF_WV) { src = Wk; off = OFF_WK; }
    else if (i < OFF_WP) { src = Wv; off = OFF_WV; }
    else if (i < OFF_WG) { src = Wp; off = OFF_WP; }
    else                 { src = Wg; off = OFF_WG; }
    float v = src[i - off];
    unsigned h = f2tf32(v);
    g_Whi[i] = h;
    g_Wlo[i] = f2tf32(__fsub_rn(v, __uint_as_float(h)));
}

// ---------------- tensor-core GEMM (3xTF32) ---------------------------------
// 128x128 CTA tile, BK=32. 8 warps (2x4), warp tile 64x32 (4x4 m16n8k8).
// Double-buffered smem stages; B arrives via cp.async (no staging regs, no
// store phase); A register-staged with fp32->tf32 hi/lo split at smem store.
// ONE __syncthreads per k-tile.
// MODE 0: C0 = acc + bias0
// MODE 1: gate — A = [A0|A1] along K; g=sigmoid(acc+bias0); C0=g*Zi+(1-g)*Zj
// MODE 2: qkv — blockIdx.y 0..5: sel=y>>1 picks (W,b,C), bn=(y&1)*128
#define GBM 128
#define GBN 128
#define GBK 32
#define AS2_LD 36                              // uint2 stride
#define BS_LD 136                              // u32 stride
#define STG_A_BYTES (GBM * AS2_LD * 8)         // 36864
#define STG_B (GBK * BS_LD)                    // 4352 u32 per array
#define STAGE_BYTES (STG_A_BYTES + 2 * STG_B * 4)   // 71680
#define GEMM_SMEM (2 * STAGE_BYTES)            // 143360

template<int MODE>
__global__ __launch_bounds__(256)
void gemm_tc(const float* __restrict__ A0, const float* __restrict__ A1,
             const unsigned* __restrict__ BhiBase, const unsigned* __restrict__ BloBase,
             const float* __restrict__ b0, const float* __restrict__ b1,
             const float* __restrict__ b2,
             const float* __restrict__ Zi, const float* __restrict__ Zj,
             float* __restrict__ C0, float* __restrict__ C1, float* __restrict__ C2,
             int M, int K)
{
    extern __shared__ char sm[];

    const int N = DMODEL;

    const int sel = (MODE == 2) ? (blockIdx.y >> 1) : 0;
    const int bn  = (MODE == 2) ? (blockIdx.y & 1) * GBN : blockIdx.y * GBN;
    const unsigned* Bhi = BhiBase + (MODE == 2 ? sel * 65536 : 0);
    const unsigned* Blo = BloBase + (MODE == 2 ? sel * 65536 : 0);
    const float* bias = (MODE == 2) ? (sel == 0 ? b0 : (sel == 1 ? b1 : b2)) : b0;
    float* C          = (MODE == 2) ? (sel == 0 ? C0 : (sel == 1 ? C1 : C2)) : C0;

    const int bm = blockIdx.x * GBM;
    const int tid  = threadIdx.x;
    const int wid  = tid >> 5;
    const int lane = tid & 31;
    const int rb = (wid >> 2) * 64;
    const int cb = (wid & 3) * 32;
    const int g   = lane >> 2;
    const int tig = lane & 3;

    float4 apf[4];

    float4 acc[4][4];
#pragma unroll
    for (int mt = 0; mt < 4; mt++)
#pragma unroll
        for (int nt = 0; nt < 4; nt++) acc[mt][nt] = make_float4(0.f, 0.f, 0.f, 0.f);

    auto stageA = [&](int s) { return (uint2*)(sm + s * STAGE_BYTES); };
    auto stageBH = [&](int s) { return (unsigned*)(sm + s * STAGE_BYTES + STG_A_BYTES); };

    // A tile -> registers (128x32 fp32 = 1024 float4-slots)
    auto ldgA = [&](int kt) {
#pragma unroll
        for (int i = 0; i < 4; i++) {
            int idx = tid + i * 256;
            int row = idx >> 3;
            int c4  = idx & 7;
            int gm  = bm + row;
            int gk  = kt + c4 * 4;
            float4 v = make_float4(0.f, 0.f, 0.f, 0.f);
            if (gm < M) {
                if (MODE == 1) {
                    const float* Ap = (gk < DMODEL) ? A0 : A1;
                    int col = gk & (DMODEL - 1);
                    v = *(const float4*)&Ap[(size_t)gm * DMODEL + col];
                } else {
                    v = *(const float4*)&A0[(size_t)gm * K + gk];
                }
            }
            apf[i] = v;
        }
    };
    // B tile -> smem via cp.async (32x128 u32 per array, 16B chunks)
    auto issueB = [&](int kt, int s) {
        unsigned* BsH = stageBH(s);
        unsigned* BsL = BsH + STG_B;
#pragma unroll
        for (int i = 0; i < 4; i++) {
            int idx = tid + i * 256;         // 0..1023
            int row = idx >> 5;              // 0..31
            int ch  = idx & 31;              // 0..31
            size_t gi = (size_t)(kt + row) * N + bn + ch * 4;
            cp16(&BsH[row * BS_LD + ch * 4], &Bhi[gi]);
            cp16(&BsL[row * BS_LD + ch * 4], &Blo[gi]);
        }
    };
    // A registers -> smem with tf32 hi/lo split
    auto storeA = [&](int s) {
        uint2* As2 = stageA(s);
#pragma unroll
        for (int i = 0; i < 4; i++) {
            int idx = tid + i * 256;
            int row = idx >> 3;
            int c4  = idx & 7;
            float4 v = apf[i];
            unsigned h0 = f2tf32(v.x), h1 = f2tf32(v.y), h2 = f2tf32(v.z), h3 = f2tf32(v.w);
            unsigned l0 = f2tf32(__fsub_rn(v.x, __uint_as_float(h0)));
            unsigned l1 = f2tf32(__fsub_rn(v.y, __uint_as_float(h1)));
            unsigned l2 = f2tf32(__fsub_rn(v.z, __uint_as_float(h2)));
            unsigned l3 = f2tf32(__fsub_rn(v.w, __uint_as_float(h3)));
            uint4* p = (uint4*)&As2[row * AS2_LD + c4 * 4];
            p[0] = make_uint4(h0, l0, h1, l1);
            p[1] = make_uint4(h2, l2, h3, l3);
        }
    };

    // ---- prologue: stage 0
    ldgA(0);
    issueB(0, 0);
    cp_commit();
    storeA(0);
    cp_wait<0>();
    __syncthreads();

    const int n_tiles = K / GBK;
    for (int t = 0; t < n_tiles; t++) {
        const bool has_next = (t + 1) < n_tiles;
        if (has_next) {
            ldgA((t + 1) * GBK);
            issueB((t + 1) * GBK, (t + 1) & 1);
            cp_commit();
        }

        const uint2*    As2 = stageA(t & 1);
        const unsigned* BsH = stageBH(t & 1);
        const unsigned* BsL = BsH + STG_B;

#pragma unroll
        for (int s = 0; s < 4; s++) {
            const int k0 = s * 8;
            unsigned ahi[4][4], alo[4][4];
#pragma unroll
            for (int mt = 0; mt < 4; mt++) {
                const int r0 = (rb + mt * 16 + g) * AS2_LD + k0;
                uint2 v0 = As2[r0 + tig];
                uint2 v1 = As2[r0 + 8 * AS2_LD + tig];
                uint2 v2 = As2[r0 + tig + 4];
                uint2 v3 = As2[r0 + 8 * AS2_LD + tig + 4];
                ahi[mt][0] = v0.x; alo[mt][0] = v0.y;
                ahi[mt][1] = v1.x; alo[mt][1] = v1.y;
                ahi[mt][2] = v2.x; alo[mt][2] = v2.y;
                ahi[mt][3] = v3.x; alo[mt][3] = v3.y;
            }
            unsigned bhi[4][2], blo[4][2];
#pragma unroll
            for (int nt = 0; nt < 4; nt++) {
                const int c0 = cb + nt * 8 + g;
                bhi[nt][0] = BsH[(k0 + tig) * BS_LD + c0];
                bhi[nt][1] = BsH[(k0 + tig + 4) * BS_LD + c0];
                blo[nt][0] = BsL[(k0 + tig) * BS_LD + c0];
                blo[nt][1] = BsL[(k0 + tig + 4) * BS_LD + c0];
            }
#pragma unroll
            for (int mt = 0; mt < 4; mt++)
#pragma unroll
                for (int nt = 0; nt < 4; nt++) {
                    mma_tf32(acc[mt][nt], ahi[mt], bhi[nt]);
                    mma_tf32(acc[mt][nt], ahi[mt], blo[nt]);
                    mma_tf32(acc[mt][nt], alo[mt], bhi[nt]);
                }
        }

        if (has_next) {
            storeA((t + 1) & 1);   // other stage: safe while peers still compute
            cp_wait<0>();          // B(t+1) landed
            __syncthreads();       // ONE barrier per k-tile
        }
    }

    // ---- epilogue
#pragma unroll
    for (int nt = 0; nt < 4; nt++) {
        const int col = bn + cb + nt * 8 + tig * 2;
        const float bv0 = bias[col];
        const float bv1 = bias[col + 1];
#pragma unroll
        for (int mt = 0; mt < 4; mt++) {
            const int row0 = bm + rb + mt * 16 + g;
            const int row1 = row0 + 8;
            const float4 a = acc[mt][nt];
            if (MODE != 1) {
                if (row0 < M) {
                    float2 o = make_float2(a.x + bv0, a.y + bv1);
                    *(float2*)&C[(size_t)row0 * N + col] = o;
                }
                if (row1 < M) {
                    float2 o = make_float2(a.z + bv0, a.w + bv1);
                    *(float2*)&C[(size_t)row1 * N + col] = o;
                }
            } else {
                if (row0 < M) {
                    size_t base = (size_t)row0 * N + col;
                    float2 zi = *(const float2*)&Zi[base];
                    float2 zj = *(const float2*)&Zj[base];
                    float g0 = 1.f / (1.f + __expf(-(a.x + bv0)));
                    float g1 = 1.f / (1.f + __expf(-(a.y + bv1)));
                    float2 o = make_float2(g0 * zi.x + (1.f - g0) * zj.x,
                                           g1 * zi.y + (1.f - g1) * zj.y);
                    *(float2*)&C[base] = o;
                }
                if (row1 < M) {
                    size_t base = (size_t)row1 * N + col;
                    float2 zi = *(const float2*)&Zi[base];
                    float2 zj = *(const float2*)&Zj[base];
                    float g0 = 1.f / (1.f + __expf(-(a.z + bv0)));
                    float g1 = 1.f / (1.f + __expf(-(a.w + bv1)));
                    float2 o = make_float2(g0 * zi.x + (1.f - g0) * zj.x,
                                           g1 * zi.y + (1.f - g1) * zj.y);
                    *(float2*)&C[base] = o;
                }
            }
        }
    }
}

// ---------------- MMA attention (round-8, unchanged) -------------------------
#define KV_LD 36    // uint2 stride
#define P_LD 40     // f32 stride
#define ATTN_SMEM (224*KV_LD*8*2 + 8*32*P_LD*4*2)   // 210944 B

__global__ __launch_bounds__(256)
void attn_mma(const float* __restrict__ Q, const float* __restrict__ K,
              const float* __restrict__ V,
              float* __restrict__ Zi, float* __restrict__ Zj)
{
    extern __shared__ char smraw[];
    uint2* Ks = (uint2*)smraw;               // [224][36]
    uint2* Vs = Ks + 224 * KV_LD;            // [224][36]
    float* Pw  = (float*)(Vs + 224 * KV_LD); // [8][32*40]
    float* Piw = Pw + 8 * 32 * P_LD;         // [8][32*40]

    const int bt = blockIdx.x >> 3;
    const int h  = blockIdx.x & 7;
    const size_t base = ((size_t)bt * NNODE) * DMODEL + h * DHEAD;
    const int tid = threadIdx.x;
    const int w = tid >> 5, lane = tid & 31;
    const int g = lane >> 2, tig = lane & 3;

    for (int idx = tid; idx < 224 * 32; idx += 256) {
        int row = idx >> 5, col = idx & 31;
        float kv = 0.f, vv = 0.f;
        if (row < NNODE) {
            kv = K[base + (size_t)row * DMODEL + col];
            vv = V[base + (size_t)row * DMODEL + col];
        }
        Ks[row * KV_LD + col] = split2(kv);
        Vs[row * KV_LD + col] = split2(vv);
    }

    float* myP  = Pw  + w * (32 * P_LD);
    float* myPi = Piw + w * (32 * P_LD);
    for (int i = lane; i < 32 * P_LD; i += 32) myPi[i] = 0.f;

    const float scale = 0.1767766952966369f; // 1/sqrt(32)
    unsigned qh[2][4][4], ql[2][4][4];
#pragma unroll
    for (int mt = 0; mt < 2; mt++)
#pragma unroll
        for (int ks = 0; ks < 4; ks++) {
            int r0 = mt * 16 + g, r1 = r0 + 8;
            int n0 = w + 8 * r0; if (n0 > 206) n0 = 206;
            int n1 = w + 8 * r1; if (n1 > 206) n1 = 206;
            int k0 = 8 * ks + tig;
            float a0 = Q[base + (size_t)n0 * DMODEL + k0] * scale;
            float a1 = Q[base + (size_t)n1 * DMODEL + k0] * scale;
            float a2 = Q[base + (size_t)n0 * DMODEL + k0 + 4] * scale;
            float a3 = Q[base + (size_t)n1 * DMODEL + k0 + 4] * scale;
            uint2 s0 = split2(a0), s1 = split2(a1), s2 = split2(a2), s3 = split2(a3);
            qh[mt][ks][0] = s0.x; ql[mt][ks][0] = s0.y;
            qh[mt][ks][1] = s1.x; ql[mt][ks][1] = s1.y;
            qh[mt][ks][2] = s2.x; ql[mt][ks][2] = s2.y;
            qh[mt][ks][3] = s3.x; ql[mt][ks][3] = s3.y;
        }
    __syncthreads();

    float4 zall[2][4], zint[2][4];
#pragma unroll
    for (int mt = 0; mt < 2; mt++)
#pragma unroll
        for (int nt = 0; nt < 4; nt++) {
            zall[mt][nt] = make_float4(0.f, 0.f, 0.f, 0.f);
            zint[mt][nt] = make_float4(0.f, 0.f, 0.f, 0.f);
        }
    float sa[4] = {0.f, 0.f, 0.f, 0.f};
    float si[4] = {0.f, 0.f, 0.f, 0.f};
    const bool isHolder = (tig == (w >> 1));
    const int wodd = w & 1;

    for (int ct = 0; ct < 7; ct++) {
        const int mbase = 32 * ct;

        float4 sacc[2][4];
#pragma unroll
        for (int mt = 0; mt < 2; mt++)
#pragma unroll
            for (int nt = 0; nt < 4; nt++) sacc[mt][nt] = make_float4(0.f, 0.f, 0.f, 0.f);

#pragma unroll
        for (int ks = 0; ks < 4; ks++)
#pragma unroll
            for (int nt = 0; nt < 4; nt++) {
                int mrow = (mbase + 8 * nt + g) * KV_LD;
                uint2 kb0 = Ks[mrow + 8 * ks + tig];
                uint2 kb1 = Ks[mrow + 8 * ks + tig + 4];
                unsigned bh[2] = {kb0.x, kb1.x};
                unsigned bl[2] = {kb0.y, kb1.y};
#pragma unroll
                for (int mt = 0; mt < 2; mt++) {
                    mma_tf32(sacc[mt][nt], qh[mt][ks], bh);
                    mma_tf32(sacc[mt][nt], qh[mt][ks], bl);
                    mma_tf32(sacc[mt][nt], ql[mt][ks], bh);
                }
            }

#pragma unroll
        for (int mt = 0; mt < 2; mt++)
#pragma unroll
            for (int nt = 0; nt < 4; nt++) {
                float4 c = sacc[mt][nt];
                int m0 = mbase + 8 * nt + 2 * tig, m1 = m0 + 1;
                int r0 = mt * 16 + g, r1 = r0 + 8;
                int n0 = w + 8 * r0, n1 = w + 8 * r1;
                c.x = (m0 <= 206 && m0 != n0) ? __expf(c.x) : 0.f;
                c.y = (m1 <= 206 && m1 != n0) ? __expf(c.y) : 0.f;
                c.z = (m0 <= 206 && m0 != n1) ? __expf(c.z) : 0.f;
                c.w = (m1 <= 206 && m1 != n1) ? __expf(c.w) : 0.f;
                sa[mt * 2 + 0] += c.x + c.y;
                sa[mt * 2 + 1] += c.z + c.w;
                if (isHolder) {
                    float v0 = wodd ? c.y : c.x;
                    float v1 = wodd ? c.w : c.z;
                    si[mt * 2 + 0] += v0;
                    si[mt * 2 + 1] += v1;
                    myPi[r0 * P_LD + 4 * ct + nt] = v0;
                    myPi[r1 * P_LD + 4 * ct + nt] = v1;
                }
                *(float2*)&myP[r0 * P_LD + 8 * nt + 2 * tig] = make_float2(c.x, c.y);
                *(float2*)&myP[r1 * P_LD + 8 * nt + 2 * tig] = make_float2(c.z, c.w);
            }
        __syncwarp();

#pragma unroll
        for (int ks = 0; ks < 4; ks++) {
            unsigned ah[2][4], al[2][4];
#pragma unroll
            for (int mt = 0; mt < 2; mt++) {
                int r0 = (mt * 16 + g) * P_LD, r1 = (mt * 16 + g + 8) * P_LD;
                float p0 = myP[r0 + 8 * ks + tig];
                float p1 = myP[r1 + 8 * ks + tig];
                float p2 = myP[r0 + 8 * ks + tig + 4];
                float p3 = myP[r1 + 8 * ks + tig + 4];
                uint2 s0 = split2(p0), s1 = split2(p1), s2 = split2(p2), s3 = split2(p3);
                ah[mt][0] = s0.x; al[mt][0] = s0.y;
                ah[mt][1] = s1.x; al[mt][1] = s1.y;
                ah[mt][2] = s2.x; al[mt][2] = s2.y;
                ah[mt][3] = s3.x; al[mt][3] = s3.y;
            }
#pragma unroll
            for (int nt = 0; nt < 4; nt++) {
                int kr = mbase + 8 * ks + tig;
                uint2 vb0 = Vs[kr * KV_LD + 8 * nt + g];
                uint2 vb1 = Vs[(kr + 4) * KV_LD + 8 * nt + g];
                unsigned bh[2] = {vb0.x, vb1.x};
                unsigned bl[2] = {vb0.y, vb1.y};
#pragma unroll
                for (int mt = 0; mt < 2; mt++) {
                    mma_tf32(zall[mt][nt], ah[mt], bh);
                    mma_tf32(zall[mt][nt], ah[mt], bl);
                    mma_tf32(zall[mt][nt], al[mt], bh);
                }
            }
        }
        __syncwarp();
    }

#pragma unroll
    for (int ks = 0; ks < 4; ks++) {
        unsigned ah[2][4], al[2][4];
#pragma unroll
        for (int mt = 0; mt < 2; mt++) {
            int r0 = (mt * 16 + g) * P_LD, r1 = (mt * 16 + g + 8) * P_LD;
            float p0 = myPi[r0 + 8 * ks + tig];
            float p1 = myPi[r1 + 8 * ks + tig];
            float p2 = myPi[r0 + 8 * ks + tig + 4];
            float p3 = myPi[r1 + 8 * ks + tig + 4];
            uint2 s0 = split2(p0), s1 = split2(p1), s2 = split2(p2), s3 = split2(p3);
            ah[mt][0] = s0.x; al[mt][0] = s0.y;
            ah[mt][1] = s1.x; al[mt][1] = s1.y;
            ah[mt][2] = s2.x; al[mt][2] = s2.y;
            ah[mt][3] = s3.x; al[mt][3] = s3.y;
        }
#pragma unroll
        for (int nt = 0; nt < 4; nt++) {
            int k0 = 8 * ks + tig;
            int mk0 = w + 8 * k0;       if (mk0 > 223) mk0 = 223;
            int mk1 = w + 8 * (k0 + 4); if (mk1 > 223) mk1 = 223;
            uint2 vb0 = Vs[mk0 * KV_LD + 8 * nt + g];
            uint2 vb1 = Vs[mk1 * KV_LD + 8 * nt + g];
            unsigned bh[2] = {vb0.x, vb1.x};
            unsigned bl[2] = {vb0.y, vb1.y};
#pragma unroll
            for (int mt = 0; mt < 2; mt++) {
                mma_tf32(zint[mt][nt], ah[mt], bh);
                mma_tf32(zint[mt][nt], ah[mt], bl);
                mma_tf32(zint[mt][nt], al[mt], bh);
            }
        }
    }

    float ri[4], rj[4];
#pragma unroll
    for (int i = 0; i < 4; i++) {
        float a = sa[i], s = si[i];
        a += __shfl_xor_sync(0xffffffffu, a, 1);
        a += __shfl_xor_sync(0xffffffffu, a, 2);
        s += __shfl_xor_sync(0xffffffffu, s, 1);
        s += __shfl_xor_sync(0xffffffffu, s, 2);
        ri[i] = 1.f / s;
        rj[i] = 1.f / (a - s);
    }

    __syncwarp();
#pragma unroll
    for (int mt = 0; mt < 2; mt++)
#pragma unroll
        for (int nt = 0; nt < 4; nt++) {
            int r0 = mt * 16 + g, r1 = r0 + 8;
            float4 za = zall[mt][nt], zi4 = zint[mt][nt];
            float ri0 = ri[mt * 2], ri1 = ri[mt * 2 + 1];
            float rj0 = rj[mt * 2], rj1 = rj[mt * 2 + 1];
            *(float2*)&myP [r0 * P_LD + 8 * nt + 2 * tig] = make_float2(zi4.x * ri0, zi4.y * ri0);
            *(float2*)&myP [r1 * P_LD + 8 * nt + 2 * tig] = make_float2(zi4.z * ri1, zi4.w * ri1);
            *(float2*)&myPi[r0 * P_LD + 8 * nt + 2 * tig] = make_float2((za.x - zi4.x) * rj0, (za.y - zi4.y) * rj0);
            *(float2*)&myPi[r1 * P_LD + 8 * nt + 2 * tig] = make_float2((za.z - zi4.z) * rj1, (za.w - zi4.w) * rj1);
        }
    __syncwarp();
#pragma unroll 4
    for (int rr = 0; rr < 32; rr++) {
        int n = w + 8 * rr;
        if (n < NNODE) {
            Zi[base + (size_t)n * DMODEL + lane] = myP [rr * P_LD + lane];
            Zj[base + (size_t)n * DMODEL + lane] = myPi[rr * P_LD + lane];
        }
    }
}

// ---------------- launch --------------------------------------------------
extern "C" void kernel_launch(void* const* d_in, const int* in_sizes, int n_in,
                              void* d_out, int out_size)
{
    const float* x  = (const float*)d_in[0];
    const float* Wq = (const float*)d_in[1];
    const float* bq = (const float*)d_in[2];
    const float* Wk = (const float*)d_in[3];
    const float* bk = (const float*)d_in[4];
    const float* Wv = (const float*)d_in[5];
    const float* bv = (const float*)d_in[6];
    const float* Wg = (const float*)d_in[7];
    const float* bg = (const float*)d_in[8];
    const float* Wp = (const float*)d_in[9];
    const float* bp = (const float*)d_in[10];
    float* out = (float*)d_out;

    float *Q, *Kp, *Vp, *Zi, *Zj, *Zc;
    unsigned *Whi, *Wlo;
    cudaGetSymbolAddress((void**)&Q,  g_Q);
    cudaGetSymbolAddress((void**)&Kp, g_K);
    cudaGetSymbolAddress((void**)&Vp, g_V);
    cudaGetSymbolAddress((void**)&Zi, g_Zi);
    cudaGetSymbolAddress((void**)&Zj, g_Zj);
    cudaGetSymbolAddress((void**)&Zc, g_Zc);
    cudaGetSymbolAddress((void**)&Whi, g_Whi);
    cudaGetSymbolAddress((void**)&Wlo, g_Wlo);

    cudaFuncSetAttribute(gemm_tc<0>, cudaFuncAttributeMaxDynamicSharedMemorySize, GEMM_SMEM);
    cudaFuncSetAttribute(gemm_tc<1>, cudaFuncAttributeMaxDynamicSharedMemorySize, GEMM_SMEM);
    cudaFuncSetAttribute(gemm_tc<2>, cudaFuncAttributeMaxDynamicSharedMemorySize, GEMM_SMEM);
    cudaFuncSetAttribute(attn_mma,   cudaFuncAttributeMaxDynamicSharedMemorySize, ATTN_SMEM);

    const int mblocks = (MTOT + GBM - 1) / GBM;   // 311

    split_weights<<<(W_TOTAL + 255) / 256, 256>>>(Wq, Wk, Wv, Wp, Wg);

    gemm_tc<2><<<dim3(mblocks, 6), 256, GEMM_SMEM>>>(
        x, nullptr, Whi + OFF_WQ, Wlo + OFF_WQ, bq, bk, bv,
        nullptr, nullptr, Q, Kp, Vp, MTOT, DMODEL);

    attn_mma<<<BTT * NHEADS, 256, ATTN_SMEM>>>(Q, Kp, Vp, Zi, Zj);

    gemm_tc<1><<<dim3(mblocks, 2), 256, GEMM_SMEM>>>(
        Zi, Zj, Whi + OFF_WG, Wlo + OFF_WG, bg, nullptr, nullptr,
        Zi, Zj, Zc, nullptr, nullptr, MTOT, 2 * DMODEL);

    gemm_tc<0><<<dim3(mblocks, 2), 256, GEMM_SMEM>>>(
        Zc, nullptr, Whi + OFF_WP, Wlo + OFF_WP, bp, nullptr, nullptr,
        nullptr, nullptr, out, nullptr, nullptr, MTOT, DMODEL);
}

// round 14
// speedup vs baseline: 1.3731x; 1.2257x over previous
#include <cuda_runtime.h>
#include <cuda_bf16.h>
#include <math.h>

#define BTT 192            // B*T
#define NNODE 207
#define DMODEL 256
#define NHEADS 8
#define DHEAD 32
#define MTOT (BTT * NNODE) // 39744

// weight offsets in k-PAIR units inside g_W2 (uint2 = packed bf16 hi,lo pair)
#define OFFP_WQ 0
#define OFFP_WK 32768
#define OFFP_WV 65536
#define OFFP_WP 98304
#define OFFP_WG 131072
#define WP_TOTAL 196608

// ---------------- scratch -------------------------------------------------
__device__ float g_Q [MTOT * DMODEL];
__device__ float g_K [MTOT * DMODEL];
__device__ float g_V [MTOT * DMODEL];
__device__ float g_Zi[MTOT * DMODEL];
__device__ float g_Zj[MTOT * DMODEL];
__device__ float g_Zc[MTOT * DMODEL];
__device__ uint2 g_W2[WP_TOTAL];   // [kp][n]: .x = {bf16 hi k, hi k+1}, .y = lo pair

// ---------------- tf32 helpers (attention) ----------------------------------
__device__ __forceinline__ unsigned f2tf32(float x) {
    unsigned r;
    asm("cvt.rna.tf32.f32 %0, %1;" : "=r"(r) : "f"(x));
    return r;
}
__device__ __forceinline__ uint2 split2(float v) {
    unsigned h = f2tf32(v);
    return make_uint2(h, f2tf32(__fsub_rn(v, __uint_as_float(h))));
}
__device__ __forceinline__ void mma_tf32(float4& c, const unsigned a[4], const unsigned b[2]) {
    asm volatile(
        "mma.sync.aligned.m16n8k8.row.col.f32.tf32.tf32.f32 "
        "{%0,%1,%2,%3}, {%4,%5,%6,%7}, {%8,%9}, {%0,%1,%2,%3};"
        : "+f"(c.x), "+f"(c.y), "+f"(c.z), "+f"(c.w)
        : "r"(a[0]), "r"(a[1]), "r"(a[2]), "r"(a[3]), "r"(b[0]), "r"(b[1]));
}

// ---------------- bf16 helpers (GEMMs) --------------------------------------
__device__ __forceinline__ unsigned bf16pack(float a, float b) {
    __nv_bfloat162 t = __floats2bfloat162_rn(a, b);   // a -> low 16 bits
    return *(unsigned*)&t;
}
// split pair (k, k+1): hi pack + lo pack
__device__ __forceinline__ void bsplit2(float a, float b, unsigned& hi, unsigned& lo) {
    float ha = __bfloat162float(__float2bfloat16_rn(a));
    float hb = __bfloat162float(__float2bfloat16_rn(b));
    hi = bf16pack(ha, hb);
    lo = bf16pack(a - ha, b - hb);
}
__device__ __forceinline__ void mma_bf16(float4& c, const unsigned a[4], const unsigned b[2]) {
    asm volatile(
        "mma.sync.aligned.m16n8k16.row.col.f32.bf16.bf16.f32 "
        "{%0,%1,%2,%3}, {%4,%5,%6,%7}, {%8,%9}, {%0,%1,%2,%3};"
        : "+f"(c.x), "+f"(c.y), "+f"(c.z), "+f"(c.w)
        : "r"(a[0]), "r"(a[1]), "r"(a[2]), "r"(a[3]), "r"(b[0]), "r"(b[1]));
}
__device__ __forceinline__ void cp16(void* s, const void* g) {
    unsigned sa = (unsigned)__cvta_generic_to_shared(s);
    asm volatile("cp.async.cg.shared.global [%0], [%1], 16;\n" :: "r"(sa), "l"(g));
}
template<int N_> __device__ __forceinline__ void cp_wait() {
    asm volatile("cp.async.wait_group %0;\n" :: "n"(N_));
}
__device__ __forceinline__ void cp_commit() {
    asm volatile("cp.async.commit_group;\n");
}

// ---------------- weight pre-split (bf16 hi/lo packed k-pairs) ---------------
__global__ __launch_bounds__(256)
void split_weights(const float* __restrict__ Wq, const float* __restrict__ Wk,
                   const float* __restrict__ Wv, const float* __restrict__ Wp,
                   const float* __restrict__ Wg)
{
    int i = blockIdx.x * 256 + threadIdx.x;
    if (i >= WP_TOTAL) return;
    const float* src; int off;
    if      (i < OFFP_WK) { src = Wq; off = OFFP_WQ; }
    else if (i < OFFP_WV) { src = Wk; off = OFFP_WK; }
    else if (i < OFFP_WP) { src = Wv; off = OFFP_WV; }
    else if (i < OFFP_WG) { src = Wp; off = OFFP_WP; }
    else                  { src = Wg; off = OFFP_WG; }
    int local = i - off;
    int kp = local >> 8;          // k-pair row
    int n  = local & 255;
    float w0 = src[(size_t)(2 * kp) * DMODEL + n];
    float w1 = src[(size_t)(2 * kp + 1) * DMODEL + n];
    unsigned hi, lo;
    bsplit2(w0, w1, hi, lo);
    g_W2[i] = make_uint2(hi, lo);
}

// ---------------- tensor-core GEMM (3xBF16, m16n8k16) ------------------------
// 128x128 CTA tile, BK=32 (= 2 k16 slices). 8 warps (2x4), warp tile 64x32.
// A fp32 -> packed bf16 hi/lo pairs at smem store; B pre-split, cp.async.
// Double-buffered stages, ONE __syncthreads per k-tile.
// MODE 0: C0 = acc + bias0
// MODE 1: gate — A = [A0|A1] along K; g=sigmoid(acc+bias0); C0=g*Zi+(1-g)*Zj
// MODE 2: qkv — blockIdx.y 0..5: sel=y>>1 picks (W,b,C), bn=(y&1)*128
#define GBM 128
#define GBN 128
#define GBK 32
#define AS2_LD 20                              // uint2 stride, A [128][20]
#define BS2_LD 132                             // uint2 stride, B [16][132]
#define STG_A_BYTES (GBM * AS2_LD * 8)         // 20480
#define STG_B_BYTES (16 * BS2_LD * 8)          // 16896
#define STAGE_BYTES (STG_A_BYTES + STG_B_BYTES)// 37376
#define GEMM_SMEM (2 * STAGE_BYTES)            // 74752

template<int MODE>
__global__ __launch_bounds__(256)
void gemm_tc(const float* __restrict__ A0, const float* __restrict__ A1,
             const uint2* __restrict__ BwBase,
             const float* __restrict__ b0, const float* __restrict__ b1,
             const float* __restrict__ b2,
             const float* __restrict__ Zi, const float* __restrict__ Zj,
             float* __restrict__ C0, float* __restrict__ C1, float* __restrict__ C2,
             int M, int K)
{
    extern __shared__ char sm[];

    const int N = DMODEL;

    const int sel = (MODE == 2) ? (blockIdx.y >> 1) : 0;
    const int bn  = (MODE == 2) ? (blockIdx.y & 1) * GBN : blockIdx.y * GBN;
    const uint2* Bw = BwBase + (MODE == 2 ? sel * 32768 : 0);
    const float* bias = (MODE == 2) ? (sel == 0 ? b0 : (sel == 1 ? b1 : b2)) : b0;
    float* C          = (MODE == 2) ? (sel == 0 ? C0 : (sel == 1 ? C1 : C2)) : C0;

    const int bm = blockIdx.x * GBM;
    const int tid  = threadIdx.x;
    const int wid  = tid >> 5;
    const int lane = tid & 31;
    const int rb = (wid >> 2) * 64;
    const int cb = (wid & 3) * 32;
    const int g   = lane >> 2;
    const int tig = lane & 3;

    float4 apf[4];

    float4 acc[4][4];
#pragma unroll
    for (int mt = 0; mt < 4; mt++)
#pragma unroll
        for (int nt = 0; nt < 4; nt++) acc[mt][nt] = make_float4(0.f, 0.f, 0.f, 0.f);

    auto stageA = [&](int s) { return (uint2*)(sm + s * STAGE_BYTES); };
    auto stageB = [&](int s) { return (uint2*)(sm + s * STAGE_BYTES + STG_A_BYTES); };

    // A tile -> registers (128x32 fp32 = 1024 float4-slots)
    auto ldgA = [&](int kt) {
#pragma unroll
        for (int i = 0; i < 4; i++) {
            int idx = tid + i * 256;
            int row = idx >> 3;
            int c4  = idx & 7;
            int gm  = bm + row;
            int gk  = kt + c4 * 4;
            float4 v = make_float4(0.f, 0.f, 0.f, 0.f);
            if (gm < M) {
                if (MODE == 1) {
                    const float* Ap = (gk < DMODEL) ? A0 : A1;
                    int col = gk & (DMODEL - 1);
                    v = *(const float4*)&Ap[(size_t)gm * DMODEL + col];
                } else {
                    v = *(const float4*)&A0[(size_t)gm * K + gk];
                }
            }
            apf[i] = v;
        }
    };
    // B tile -> smem via cp.async: 16 kp-rows x 128 uint2 = 1024 16B chunks
    auto issueB = [&](int kt, int s) {
        uint2* Bs2 = stageB(s);
        const int ktp = kt >> 1;
#pragma unroll
        for (int i = 0; i < 4; i++) {
            int idx = tid + i * 256;         // 0..1023
            int row = idx >> 6;              // 0..15
            int ch  = idx & 63;              // 0..63
            cp16(&Bs2[row * BS2_LD + ch * 2],
                 &Bw[(size_t)(ktp + row) * N + bn + ch * 2]);
        }
    };
    // A registers -> smem as packed bf16 hi/lo pairs
    auto storeA = [&](int s) {
        uint2* As2 = stageA(s);
#pragma unroll
        for (int i = 0; i < 4; i++) {
            int idx = tid + i * 256;
            int row = idx >> 3;
            int c4  = idx & 7;
            float4 v = apf[i];
            unsigned hi01, lo01, hi23, lo23;
            bsplit2(v.x, v.y, hi01, lo01);
            bsplit2(v.z, v.w, hi23, lo23);
            *(uint4*)&As2[row * AS2_LD + c4 * 2] = make_uint4(hi01, lo01, hi23, lo23);
        }
    };

    // ---- prologue: stage 0
    ldgA(0);
    issueB(0, 0);
    cp_commit();
    storeA(0);
    cp_wait<0>();
    __syncthreads();

    const int n_tiles = K / GBK;
    for (int t = 0; t < n_tiles; t++) {
        const bool has_next = (t + 1) < n_tiles;
        if (has_next) {
            ldgA((t + 1) * GBK);
            issueB((t + 1) * GBK, (t + 1) & 1);
            cp_commit();
        }

        const uint2* As2 = stageA(t & 1);
        const uint2* Bs2 = stageB(t & 1);

#pragma unroll
        for (int s = 0; s < 2; s++) {          // two k16 slices
            const int kb = s * 8;              // k-pair base
            unsigned ahi[4][4], alo[4][4];
#pragma unroll
            for (int mt = 0; mt < 4; mt++) {
                const int r0 = (rb + mt * 16 + g) * AS2_LD + kb;
                uint2 v0 = As2[r0 + tig];
                uint2 v1 = As2[r0 + 8 * AS2_LD + tig];
                uint2 v2 = As2[r0 + tig + 4];
                uint2 v3 = As2[r0 + 8 * AS2_LD + tig + 4];
                ahi[mt][0] = v0.x; alo[mt][0] = v0.y;
                ahi[mt][1] = v1.x; alo[mt][1] = v1.y;
                ahi[mt][2] = v2.x; alo[mt][2] = v2.y;
                ahi[mt][3] = v3.x; alo[mt][3] = v3.y;
            }
            unsigned bhi[4][2], blo[4][2];
#pragma unroll
            for (int nt = 0; nt < 4; nt++) {
                const int c0 = cb + nt * 8 + g;
                uint2 bb0 = Bs2[(kb + tig) * BS2_LD + c0];
                uint2 bb1 = Bs2[(kb + tig + 4) * BS2_LD + c0];
                bhi[nt][0] = bb0.x; blo[nt][0] = bb0.y;
                bhi[nt][1] = bb1.x; blo[nt][1] = bb1.y;
            }
#pragma unroll
            for (int mt = 0; mt < 4; mt++)
#pragma unroll
                for (int nt = 0; nt < 4; nt++) {
                    mma_bf16(acc[mt][nt], ahi[mt], bhi[nt]);
                    mma_bf16(acc[mt][nt], ahi[mt], blo[nt]);
                    mma_bf16(acc[mt][nt], alo[mt], bhi[nt]);
                }
        }

        if (has_next) {
            storeA((t + 1) & 1);
            cp_wait<0>();
            __syncthreads();
        }
    }

    // ---- epilogue (C fragment layout identical to tf32 version)
#pragma unroll
    for (int nt = 0; nt < 4; nt++) {
        const int col = bn + cb + nt * 8 + tig * 2;
        const float bv0 = bias[col];
        const float bv1 = bias[col + 1];
#pragma unroll
        for (int mt = 0; mt < 4; mt++) {
            const int row0 = bm + rb + mt * 16 + g;
            const int row1 = row0 + 8;
            const float4 a = acc[mt][nt];
            if (MODE != 1) {
                if (row0 < M) {
                    float2 o = make_float2(a.x + bv0, a.y + bv1);
                    *(float2*)&C[(size_t)row0 * N + col] = o;
                }
                if (row1 < M) {
                    float2 o = make_float2(a.z + bv0, a.w + bv1);
                    *(float2*)&C[(size_t)row1 * N + col] = o;
                }
            } else {
                if (row0 < M) {
                    size_t base = (size_t)row0 * N + col;
                    float2 zi = *(const float2*)&Zi[base];
                    float2 zj = *(const float2*)&Zj[base];
                    float g0 = 1.f / (1.f + __expf(-(a.x + bv0)));
                    float g1 = 1.f / (1.f + __expf(-(a.y + bv1)));
                    float2 o = make_float2(g0 * zi.x + (1.f - g0) * zj.x,
                                           g1 * zi.y + (1.f - g1) * zj.y);
                    *(float2*)&C[base] = o;
                }
                if (row1 < M) {
                    size_t base = (size_t)row1 * N + col;
                    float2 zi = *(const float2*)&Zi[base];
                    float2 zj = *(const float2*)&Zj[base];
                    float g0 = 1.f / (1.f + __expf(-(a.z + bv0)));
                    float g1 = 1.f / (1.f + __expf(-(a.w + bv1)));
                    float2 o = make_float2(g0 * zi.x + (1.f - g0) * zj.x,
                                           g1 * zi.y + (1.f - g1) * zj.y);
                    *(float2*)&C[base] = o;
                }
            }
        }
    }
}

// ---------------- MMA attention (round-8, unchanged — 3xTF32) ----------------
#define KV_LD 36    // uint2 stride
#define P_LD 40     // f32 stride
#define ATTN_SMEM (224*KV_LD*8*2 + 8*32*P_LD*4*2)   // 210944 B

__global__ __launch_bounds__(256)
void attn_mma(const float* __restrict__ Q, const float* __restrict__ K,
              const float* __restrict__ V,
              float* __restrict__ Zi, float* __restrict__ Zj)
{
    extern __shared__ char smraw[];
    uint2* Ks = (uint2*)smraw;               // [224][36]
    uint2* Vs = Ks + 224 * KV_LD;            // [224][36]
    float* Pw  = (float*)(Vs + 224 * KV_LD); // [8][32*40]
    float* Piw = Pw + 8 * 32 * P_LD;         // [8][32*40]

    const int bt = blockIdx.x >> 3;
    const int h  = blockIdx.x & 7;
    const size_t base = ((size_t)bt * NNODE) * DMODEL + h * DHEAD;
    const int tid = threadIdx.x;
    const int w = tid >> 5, lane = tid & 31;
    const int g = lane >> 2, tig = lane & 3;

    for (int idx = tid; idx < 224 * 32; idx += 256) {
        int row = idx >> 5, col = idx & 31;
        float kv = 0.f, vv = 0.f;
        if (row < NNODE) {
            kv = K[base + (size_t)row * DMODEL + col];
            vv = V[base + (size_t)row * DMODEL + col];
        }
        Ks[row * KV_LD + col] = split2(kv);
        Vs[row * KV_LD + col] = split2(vv);
    }

    float* myP  = Pw  + w * (32 * P_LD);
    float* myPi = Piw + w * (32 * P_LD);
    for (int i = lane; i < 32 * P_LD; i += 32) myPi[i] = 0.f;

    const float scale = 0.1767766952966369f; // 1/sqrt(32)
    unsigned qh[2][4][4], ql[2][4][4];
#pragma unroll
    for (int mt = 0; mt < 2; mt++)
#pragma unroll
        for (int ks = 0; ks < 4; ks++) {
            int r0 = mt * 16 + g, r1 = r0 + 8;
            int n0 = w + 8 * r0; if (n0 > 206) n0 = 206;
            int n1 = w + 8 * r1; if (n1 > 206) n1 = 206;
            int k0 = 8 * ks + tig;
            float a0 = Q[base + (size_t)n0 * DMODEL + k0] * scale;
            float a1 = Q[base + (size_t)n1 * DMODEL + k0] * scale;
            float a2 = Q[base + (size_t)n0 * DMODEL + k0 + 4] * scale;
            float a3 = Q[base + (size_t)n1 * DMODEL + k0 + 4] * scale;
            uint2 s0 = split2(a0), s1 = split2(a1), s2 = split2(a2), s3 = split2(a3);
            qh[mt][ks][0] = s0.x; ql[mt][ks][0] = s0.y;
            qh[mt][ks][1] = s1.x; ql[mt][ks][1] = s1.y;
            qh[mt][ks][2] = s2.x; ql[mt][ks][2] = s2.y;
            qh[mt][ks][3] = s3.x; ql[mt][ks][3] = s3.y;
        }
    __syncthreads();

    float4 zall[2][4], zint[2][4];
#pragma unroll
    for (int mt = 0; mt < 2; mt++)
#pragma unroll
        for (int nt = 0; nt < 4; nt++) {
            zall[mt][nt] = make_float4(0.f, 0.f, 0.f, 0.f);
            zint[mt][nt] = make_float4(0.f, 0.f, 0.f, 0.f);
        }
    float sa[4] = {0.f, 0.f, 0.f, 0.f};
    float si[4] = {0.f, 0.f, 0.f, 0.f};
    const bool isHolder = (tig == (w >> 1));
    const int wodd = w & 1;

    for (int ct = 0; ct < 7; ct++) {
        const int mbase = 32 * ct;

        float4 sacc[2][4];
#pragma unroll
        for (int mt = 0; mt < 2; mt++)
#pragma unroll
            for (int nt = 0; nt < 4; nt++) sacc[mt][nt] = make_float4(0.f, 0.f, 0.f, 0.f);

#pragma unroll
        for (int ks = 0; ks < 4; ks++)
#pragma unroll
            for (int nt = 0; nt < 4; nt++) {
                int mrow = (mbase + 8 * nt + g) * KV_LD;
                uint2 kb0 = Ks[mrow + 8 * ks + tig];
                uint2 kb1 = Ks[mrow + 8 * ks + tig + 4];
                unsigned bh[2] = {kb0.x, kb1.x};
                unsigned bl[2] = {kb0.y, kb1.y};
#pragma unroll
                for (int mt = 0; mt < 2; mt++) {
                    mma_tf32(sacc[mt][nt], qh[mt][ks], bh);
                    mma_tf32(sacc[mt][nt], qh[mt][ks], bl);
                    mma_tf32(sacc[mt][nt], ql[mt][ks], bh);
                }
            }

#pragma unroll
        for (int mt = 0; mt < 2; mt++)
#pragma unroll
            for (int nt = 0; nt < 4; nt++) {
                float4 c = sacc[mt][nt];
                int m0 = mbase + 8 * nt + 2 * tig, m1 = m0 + 1;
                int r0 = mt * 16 + g, r1 = r0 + 8;
                int n0 = w + 8 * r0, n1 = w + 8 * r1;
                c.x = (m0 <= 206 && m0 != n0) ? __expf(c.x) : 0.f;
                c.y = (m1 <= 206 && m1 != n0) ? __expf(c.y) : 0.f;
                c.z = (m0 <= 206 && m0 != n1) ? __expf(c.z) : 0.f;
                c.w = (m1 <= 206 && m1 != n1) ? __expf(c.w) : 0.f;
                sa[mt * 2 + 0] += c.x + c.y;
                sa[mt * 2 + 1] += c.z + c.w;
                if (isHolder) {
                    float v0 = wodd ? c.y : c.x;
                    float v1 = wodd ? c.w : c.z;
                    si[mt * 2 + 0] += v0;
                    si[mt * 2 + 1] += v1;
                    myPi[r0 * P_LD + 4 * ct + nt] = v0;
                    myPi[r1 * P_LD + 4 * ct + nt] = v1;
                }
                *(float2*)&myP[r0 * P_LD + 8 * nt + 2 * tig] = make_float2(c.x, c.y);
                *(float2*)&myP[r1 * P_LD + 8 * nt + 2 * tig] = make_float2(c.z, c.w);
            }
        __syncwarp();

#pragma unroll
        for (int ks = 0; ks < 4; ks++) {
            unsigned ah[2][4], al[2][4];
#pragma unroll
            for (int mt = 0; mt < 2; mt++) {
                int r0 = (mt * 16 + g) * P_LD, r1 = (mt * 16 + g + 8) * P_LD;
                float p0 = myP[r0 + 8 * ks + tig];
                float p1 = myP[r1 + 8 * ks + tig];
                float p2 = myP[r0 + 8 * ks + tig + 4];
                float p3 = myP[r1 + 8 * ks + tig + 4];
                uint2 s0 = split2(p0), s1 = split2(p1), s2 = split2(p2), s3 = split2(p3);
                ah[mt][0] = s0.x; al[mt][0] = s0.y;
                ah[mt][1] = s1.x; al[mt][1] = s1.y;
                ah[mt][2] = s2.x; al[mt][2] = s2.y;
                ah[mt][3] = s3.x; al[mt][3] = s3.y;
            }
#pragma unroll
            for (int nt = 0; nt < 4; nt++) {
                int kr = mbase + 8 * ks + tig;
                uint2 vb0 = Vs[kr * KV_LD + 8 * nt + g];
                uint2 vb1 = Vs[(kr + 4) * KV_LD + 8 * nt + g];
                unsigned bh[2] = {vb0.x, vb1.x};
                unsigned bl[2] = {vb0.y, vb1.y};
#pragma unroll
                for (int mt = 0; mt < 2; mt++) {
                    mma_tf32(zall[mt][nt], ah[mt], bh);
                    mma_tf32(zall[mt][nt], ah[mt], bl);
                    mma_tf32(zall[mt][nt], al[mt], bh);
                }
            }
        }
        __syncwarp();
    }

#pragma unroll
    for (int ks = 0; ks < 4; ks++) {
        unsigned ah[2][4], al[2][4];
#pragma unroll
        for (int mt = 0; mt < 2; mt++) {
            int r0 = (mt * 16 + g) * P_LD, r1 = (mt * 16 + g + 8) * P_LD;
            float p0 = myPi[r0 + 8 * ks + tig];
            float p1 = myPi[r1 + 8 * ks + tig];
            float p2 = myPi[r0 + 8 * ks + tig + 4];
            float p3 = myPi[r1 + 8 * ks + tig + 4];
            uint2 s0 = split2(p0), s1 = split2(p1), s2 = split2(p2), s3 = split2(p3);
            ah[mt][0] = s0.x; al[mt][0] = s0.y;
            ah[mt][1] = s1.x; al[mt][1] = s1.y;
            ah[mt][2] = s2.x; al[mt][2] = s2.y;
            ah[mt][3] = s3.x; al[mt][3] = s3.y;
        }
#pragma unroll
        for (int nt = 0; nt < 4; nt++) {
            int k0 = 8 * ks + tig;
            int mk0 = w + 8 * k0;       if (mk0 > 223) mk0 = 223;
            int mk1 = w + 8 * (k0 + 4); if (mk1 > 223) mk1 = 223;
            uint2 vb0 = Vs[mk0 * KV_LD + 8 * nt + g];
            uint2 vb1 = Vs[mk1 * KV_LD + 8 * nt + g];
            unsigned bh[2] = {vb0.x, vb1.x};
            unsigned bl[2] = {vb0.y, vb1.y};
#pragma unroll
            for (int mt = 0; mt < 2; mt++) {
                mma_tf32(zint[mt][nt], ah[mt], bh);
                mma_tf32(zint[mt][nt], ah[mt], bl);
                mma_tf32(zint[mt][nt], al[mt], bh);
            }
        }
    }

    float ri[4], rj[4];
#pragma unroll
    for (int i = 0; i < 4; i++) {
        float a = sa[i], s = si[i];
        a += __shfl_xor_sync(0xffffffffu, a, 1);
        a += __shfl_xor_sync(0xffffffffu, a, 2);
        s += __shfl_xor_sync(0xffffffffu, s, 1);
        s += __shfl_xor_sync(0xffffffffu, s, 2);
        ri[i] = 1.f / s;
        rj[i] = 1.f / (a - s);
    }

    __syncwarp();
#pragma unroll
    for (int mt = 0; mt < 2; mt++)
#pragma unroll
        for (int nt = 0; nt < 4; nt++) {
            int r0 = mt * 16 + g, r1 = r0 + 8;
            float4 za = zall[mt][nt], zi4 = zint[mt][nt];
            float ri0 = ri[mt * 2], ri1 = ri[mt * 2 + 1];
            float rj0 = rj[mt * 2], rj1 = rj[mt * 2 + 1];
            *(float2*)&myP [r0 * P_LD + 8 * nt + 2 * tig] = make_float2(zi4.x * ri0, zi4.y * ri0);
            *(float2*)&myP [r1 * P_LD + 8 * nt + 2 * tig] = make_float2(zi4.z * ri1, zi4.w * ri1);
            *(float2*)&myPi[r0 * P_LD + 8 * nt + 2 * tig] = make_float2((za.x - zi4.x) * rj0, (za.y - zi4.y) * rj0);
            *(float2*)&myPi[r1 * P_LD + 8 * nt + 2 * tig] = make_float2((za.z - zi4.z) * rj1, (za.w - zi4.w) * rj1);
        }
    __syncwarp();
#pragma unroll 4
    for (int rr = 0; rr < 32; rr++) {
        int n = w + 8 * rr;
        if (n < NNODE) {
            Zi[base + (size_t)n * DMODEL + lane] = myP [rr * P_LD + lane];
            Zj[base + (size_t)n * DMODEL + lane] = myPi[rr * P_LD + lane];
        }
    }
}

// ---------------- launch --------------------------------------------------
extern "C" void kernel_launch(void* const* d_in, const int* in_sizes, int n_in,
                              void* d_out, int out_size)
{
    const float* x  = (const float*)d_in[0];
    const float* Wq = (const float*)d_in[1];
    const float* bq = (const float*)d_in[2];
    const float* Wk = (const float*)d_in[3];
    const float* bk = (const float*)d_in[4];
    const float* Wv = (const float*)d_in[5];
    const float* bv = (const float*)d_in[6];
    const float* Wg = (const float*)d_in[7];
    const float* bg = (const float*)d_in[8];
    const float* Wp = (const float*)d_in[9];
    const float* bp = (const float*)d_in[10];
    float* out = (float*)d_out;

    float *Q, *Kp, *Vp, *Zi, *Zj, *Zc;
    uint2 *W2;
    cudaGetSymbolAddress((void**)&Q,  g_Q);
    cudaGetSymbolAddress((void**)&Kp, g_K);
    cudaGetSymbolAddress((void**)&Vp, g_V);
    cudaGetSymbolAddress((void**)&Zi, g_Zi);
    cudaGetSymbolAddress((void**)&Zj, g_Zj);
    cudaGetSymbolAddress((void**)&Zc, g_Zc);
    cudaGetSymbolAddress((void**)&W2, g_W2);

    cudaFuncSetAttribute(gemm_tc<0>, cudaFuncAttributeMaxDynamicSharedMemorySize, GEMM_SMEM);
    cudaFuncSetAttribute(gemm_tc<1>, cudaFuncAttributeMaxDynamicSharedMemorySize, GEMM_SMEM);
    cudaFuncSetAttribute(gemm_tc<2>, cudaFuncAttributeMaxDynamicSharedMemorySize, GEMM_SMEM);
    cudaFuncSetAttribute(attn_mma,   cudaFuncAttributeMaxDynamicSharedMemorySize, ATTN_SMEM);

    const int mblocks = (MTOT + GBM - 1) / GBM;   // 311

    split_weights<<<(WP_TOTAL + 255) / 256, 256>>>(Wq, Wk, Wv, Wp, Wg);

    gemm_tc<2><<<dim3(mblocks, 6), 256, GEMM_SMEM>>>(
        x, nullptr, W2 + OFFP_WQ, bq, bk, bv,
        nullptr, nullptr, Q, Kp, Vp, MTOT, DMODEL);

    attn_mma<<<BTT * NHEADS, 256, ATTN_SMEM>>>(Q, Kp, Vp, Zi, Zj);

    gemm_tc<1><<<dim3(mblocks, 2), 256, GEMM_SMEM>>>(
        Zi, Zj, W2 + OFFP_WG, bg, nullptr, nullptr,
        Zi, Zj, Zc, nullptr, nullptr, MTOT, 2 * DMODEL);

    gemm_tc<0><<<dim3(mblocks, 2), 256, GEMM_SMEM>>>(
        Zc, nullptr, W2 + OFFP_WP, bp, nullptr, nullptr,
        nullptr, nullptr, out, nullptr, nullptr, MTOT, DMODEL);
}

// round 16
// speedup vs baseline: 1.5556x; 1.1329x over previous
#include <cuda_runtime.h>
#include <cuda_bf16.h>
#include <math.h>

#define BTT 192            // B*T
#define NNODE 207
#define DMODEL 256
#define NHEADS 8
#define DHEAD 32
#define MTOT (BTT * NNODE) // 39744

// weight offsets in k-PAIR units inside g_W2 (uint2 = packed bf16 hi,lo pair)
#define OFFP_WQ 0
#define OFFP_WK 32768
#define OFFP_WV 65536
#define OFFP_WP 98304
#define OFFP_WG 131072
#define WP_TOTAL 196608

// ---------------- scratch -------------------------------------------------
__device__ float g_Q [MTOT * DMODEL];
__device__ float g_K [MTOT * DMODEL];
__device__ float g_V [MTOT * DMODEL];
__device__ float g_Zi[MTOT * DMODEL];
__device__ float g_Zj[MTOT * DMODEL];
__device__ float g_Zc[MTOT * DMODEL];
__device__ uint2 g_W2[WP_TOTAL];   // [kp][n]: .x = {bf16 hi k, hi k+1}, .y = lo pair

// ---------------- tf32 helpers (attention) ----------------------------------
__device__ __forceinline__ unsigned f2tf32(float x) {
    unsigned r;
    asm("cvt.rna.tf32.f32 %0, %1;" : "=r"(r) : "f"(x));
    return r;
}
__device__ __forceinline__ uint2 split2(float v) {
    unsigned h = f2tf32(v);
    return make_uint2(h, f2tf32(__fsub_rn(v, __uint_as_float(h))));
}
__device__ __forceinline__ void mma_tf32(float4& c, const unsigned a[4], const unsigned b[2]) {
    asm volatile(
        "mma.sync.aligned.m16n8k8.row.col.f32.tf32.tf32.f32 "
        "{%0,%1,%2,%3}, {%4,%5,%6,%7}, {%8,%9}, {%0,%1,%2,%3};"
        : "+f"(c.x), "+f"(c.y), "+f"(c.z), "+f"(c.w)
        : "r"(a[0]), "r"(a[1]), "r"(a[2]), "r"(a[3]), "r"(b[0]), "r"(b[1]));
}

// ---------------- bf16 helpers (GEMMs) --------------------------------------
__device__ __forceinline__ unsigned bf16pack(float a, float b) {
    __nv_bfloat162 t = __floats2bfloat162_rn(a, b);   // a -> low 16 bits
    return *(unsigned*)&t;
}
// split pair (k, k+1): hi pack + lo pack
__device__ __forceinline__ void bsplit2(float a, float b, unsigned& hi, unsigned& lo) {
    float ha = __bfloat162float(__float2bfloat16_rn(a));
    float hb = __bfloat162float(__float2bfloat16_rn(b));
    hi = bf16pack(ha, hb);
    lo = bf16pack(a - ha, b - hb);
}
__device__ __forceinline__ void mma_bf16(float4& c, const unsigned a[4], const unsigned b[2]) {
    asm volatile(
        "mma.sync.aligned.m16n8k16.row.col.f32.bf16.bf16.f32 "
        "{%0,%1,%2,%3}, {%4,%5,%6,%7}, {%8,%9}, {%0,%1,%2,%3};"
        : "+f"(c.x), "+f"(c.y), "+f"(c.z), "+f"(c.w)
        : "r"(a[0]), "r"(a[1]), "r"(a[2]), "r"(a[3]), "r"(b[0]), "r"(b[1]));
}
__device__ __forceinline__ void cp16(void* s, const void* g) {
    unsigned sa = (unsigned)__cvta_generic_to_shared(s);
    asm volatile("cp.async.cg.shared.global [%0], [%1], 16;\n" :: "r"(sa), "l"(g));
}
template<int N_> __device__ __forceinline__ void cp_wait() {
    asm volatile("cp.async.wait_group %0;\n" :: "n"(N_));
}
__device__ __forceinline__ void cp_commit() {
    asm volatile("cp.async.commit_group;\n");
}

// ---------------- weight pre-split (bf16 hi/lo packed k-pairs) ---------------
__global__ __launch_bounds__(256)
void split_weights(const float* __restrict__ Wq, const float* __restrict__ Wk,
                   const float* __restrict__ Wv, const float* __restrict__ Wp,
                   const float* __restrict__ Wg)
{
    int i = blockIdx.x * 256 + threadIdx.x;
    if (i >= WP_TOTAL) return;
    const float* src; int off;
    if      (i < OFFP_WK) { src = Wq; off = OFFP_WQ; }
    else if (i < OFFP_WV) { src = Wk; off = OFFP_WK; }
    else if (i < OFFP_WP) { src = Wv; off = OFFP_WV; }
    else if (i < OFFP_WG) { src = Wp; off = OFFP_WP; }
    else                  { src = Wg; off = OFFP_WG; }
    int local = i - off;
    int kp = local >> 8;          // k-pair row
    int n  = local & 255;
    float w0 = src[(size_t)(2 * kp) * DMODEL + n];
    float w1 = src[(size_t)(2 * kp + 1) * DMODEL + n];
    unsigned hi, lo;
    bsplit2(w0, w1, hi, lo);
    g_W2[i] = make_uint2(hi, lo);
}

// ---------------- tensor-core GEMM (3xBF16, m16n8k16), 2 CTAs/SM -------------
// 128x128 CTA tile, BK=32 (= 2 k16 slices). 8 warps (2x4), warp tile 64x32.
// A fp32 -> packed bf16 hi/lo pairs at smem store; B pre-split, cp.async.
// Double-buffered stages, ONE __syncthreads per k-tile.
// __launch_bounds__(256, 2): regs 132 -> 128 (exact RF fit for 2 CTAs/SM).
// MODE 0: C0 = acc + bias0
// MODE 1: gate — A = [A0|A1] along K; g=sigmoid(acc+bias0); C0=g*Zi+(1-g)*Zj
// MODE 2: qkv — blockIdx.y 0..5: sel=y>>1 picks (W,b,C), bn=(y&1)*128
#define GBM 128
#define GBN 128
#define GBK 32
#define AS2_LD 20                              // uint2 stride, A [128][20]
#define BS2_LD 132                             // uint2 stride, B [16][132]
#define STG_A_BYTES (GBM * AS2_LD * 8)         // 20480
#define STG_B_BYTES (16 * BS2_LD * 8)          // 16896
#define STAGE_BYTES (STG_A_BYTES + STG_B_BYTES)// 37376
#define GEMM_SMEM (2 * STAGE_BYTES)            // 74752

template<int MODE>
__global__ __launch_bounds__(256, 2)
void gemm_tc(const float* __restrict__ A0, const float* __restrict__ A1,
             const uint2* __restrict__ BwBase,
             const float* __restrict__ b0, const float* __restrict__ b1,
             const float* __restrict__ b2,
             const float* __restrict__ Zi, const float* __restrict__ Zj,
             float* __restrict__ C0, float* __restrict__ C1, float* __restrict__ C2,
             int M, int K)
{
    extern __shared__ char sm[];

    const int N = DMODEL;

    const int sel = (MODE == 2) ? (blockIdx.y >> 1) : 0;
    const int bn  = (MODE == 2) ? (blockIdx.y & 1) * GBN : blockIdx.y * GBN;
    const uint2* Bw = BwBase + (MODE == 2 ? sel * 32768 : 0);
    const float* bias = (MODE == 2) ? (sel == 0 ? b0 : (sel == 1 ? b1 : b2)) : b0;
    float* C          = (MODE == 2) ? (sel == 0 ? C0 : (sel == 1 ? C1 : C2)) : C0;

    const int bm = blockIdx.x * GBM;
    const int tid  = threadIdx.x;
    const int wid  = tid >> 5;
    const int lane = tid & 31;
    const int rb = (wid >> 2) * 64;
    const int cb = (wid & 3) * 32;
    const int g   = lane >> 2;
    const int tig = lane & 3;

    float4 apf[4];

    float4 acc[4][4];
#pragma unroll
    for (int mt = 0; mt < 4; mt++)
#pragma unroll
        for (int nt = 0; nt < 4; nt++) acc[mt][nt] = make_float4(0.f, 0.f, 0.f, 0.f);

    auto stageA = [&](int s) { return (uint2*)(sm + s * STAGE_BYTES); };
    auto stageB = [&](int s) { return (uint2*)(sm + s * STAGE_BYTES + STG_A_BYTES); };

    // A tile -> registers (128x32 fp32 = 1024 float4-slots)
    auto ldgA = [&](int kt) {
#pragma unroll
        for (int i = 0; i < 4; i++) {
            int idx = tid + i * 256;
            int row = idx >> 3;
            int c4  = idx & 7;
            int gm  = bm + row;
            int gk  = kt + c4 * 4;
            float4 v = make_float4(0.f, 0.f, 0.f, 0.f);
            if (gm < M) {
                if (MODE == 1) {
                    const float* Ap = (gk < DMODEL) ? A0 : A1;
                    int col = gk & (DMODEL - 1);
                    v = *(const float4*)&Ap[(size_t)gm * DMODEL + col];
                } else {
                    v = *(const float4*)&A0[(size_t)gm * K + gk];
                }
            }
            apf[i] = v;
        }
    };
    // B tile -> smem via cp.async: 16 kp-rows x 128 uint2 = 1024 16B chunks
    auto issueB = [&](int kt, int s) {
        uint2* Bs2 = stageB(s);
        const int ktp = kt >> 1;
#pragma unroll
        for (int i = 0; i < 4; i++) {
            int idx = tid + i * 256;         // 0..1023
            int row = idx >> 6;              // 0..15
            int ch  = idx & 63;              // 0..63
            cp16(&Bs2[row * BS2_LD + ch * 2],
                 &Bw[(size_t)(ktp + row) * N + bn + ch * 2]);
        }
    };
    // A registers -> smem as packed bf16 hi/lo pairs
    auto storeA = [&](int s) {
        uint2* As2 = stageA(s);
#pragma unroll
        for (int i = 0; i < 4; i++) {
            int idx = tid + i * 256;
            int row = idx >> 3;
            int c4  = idx & 7;
            float4 v = apf[i];
            unsigned hi01, lo01, hi23, lo23;
            bsplit2(v.x, v.y, hi01, lo01);
            bsplit2(v.z, v.w, hi23, lo23);
            *(uint4*)&As2[row * AS2_LD + c4 * 2] = make_uint4(hi01, lo01, hi23, lo23);
        }
    };

    // ---- prologue: stage 0
    ldgA(0);
    issueB(0, 0);
    cp_commit();
    storeA(0);
    cp_wait<0>();
    __syncthreads();

    const int n_tiles = K / GBK;
    for (int t = 0; t < n_tiles; t++) {
        const bool has_next = (t + 1) < n_tiles;
        if (has_next) {
            ldgA((t + 1) * GBK);
            issueB((t + 1) * GBK, (t + 1) & 1);
            cp_commit();
        }

        const uint2* As2 = stageA(t & 1);
        const uint2* Bs2 = stageB(t & 1);

#pragma unroll
        for (int s = 0; s < 2; s++) {          // two k16 slices
            const int kb = s * 8;              // k-pair base
            unsigned ahi[4][4], alo[4][4];
#pragma unroll
            for (int mt = 0; mt < 4; mt++) {
                const int r0 = (rb + mt * 16 + g) * AS2_LD + kb;
                uint2 v0 = As2[r0 + tig];
                uint2 v1 = As2[r0 + 8 * AS2_LD + tig];
                uint2 v2 = As2[r0 + tig + 4];
                uint2 v3 = As2[r0 + 8 * AS2_LD + tig + 4];
                ahi[mt][0] = v0.x; alo[mt][0] = v0.y;
                ahi[mt][1] = v1.x; alo[mt][1] = v1.y;
                ahi[mt][2] = v2.x; alo[mt][2] = v2.y;
                ahi[mt][3] = v3.x; alo[mt][3] = v3.y;
            }
            unsigned bhi[4][2], blo[4][2];
#pragma unroll
            for (int nt = 0; nt < 4; nt++) {
                const int c0 = cb + nt * 8 + g;
                uint2 bb0 = Bs2[(kb + tig) * BS2_LD + c0];
                uint2 bb1 = Bs2[(kb + tig + 4) * BS2_LD + c0];
                bhi[nt][0] = bb0.x; blo[nt][0] = bb0.y;
                bhi[nt][1] = bb1.x; blo[nt][1] = bb1.y;
            }
#pragma unroll
            for (int mt = 0; mt < 4; mt++)
#pragma unroll
                for (int nt = 0; nt < 4; nt++) {
                    mma_bf16(acc[mt][nt], ahi[mt], bhi[nt]);
                    mma_bf16(acc[mt][nt], ahi[mt], blo[nt]);
                    mma_bf16(acc[mt][nt], alo[mt], bhi[nt]);
                }
        }

        if (has_next) {
            storeA((t + 1) & 1);
            cp_wait<0>();
            __syncthreads();
        }
    }

    // ---- epilogue (C fragment layout identical to tf32 version)
#pragma unroll
    for (int nt = 0; nt < 4; nt++) {
        const int col = bn + cb + nt * 8 + tig * 2;
        const float bv0 = bias[col];
        const float bv1 = bias[col + 1];
#pragma unroll
        for (int mt = 0; mt < 4; mt++) {
            const int row0 = bm + rb + mt * 16 + g;
            const int row1 = row0 + 8;
            const float4 a = acc[mt][nt];
            if (MODE != 1) {
                if (row0 < M) {
                    float2 o = make_float2(a.x + bv0, a.y + bv1);
                    *(float2*)&C[(size_t)row0 * N + col] = o;
                }
                if (row1 < M) {
                    float2 o = make_float2(a.z + bv0, a.w + bv1);
                    *(float2*)&C[(size_t)row1 * N + col] = o;
                }
            } else {
                if (row0 < M) {
                    size_t base = (size_t)row0 * N + col;
                    float2 zi = *(const float2*)&Zi[base];
                    float2 zj = *(const float2*)&Zj[base];
                    float g0 = 1.f / (1.f + __expf(-(a.x + bv0)));
                    float g1 = 1.f / (1.f + __expf(-(a.y + bv1)));
                    float2 o = make_float2(g0 * zi.x + (1.f - g0) * zj.x,
                                           g1 * zi.y + (1.f - g1) * zj.y);
                    *(float2*)&C[base] = o;
                }
                if (row1 < M) {
                    size_t base = (size_t)row1 * N + col;
                    float2 zi = *(const float2*)&Zi[base];
                    float2 zj = *(const float2*)&Zj[base];
                    float g0 = 1.f / (1.f + __expf(-(a.z + bv0)));
                    float g1 = 1.f / (1.f + __expf(-(a.w + bv1)));
                    float2 o = make_float2(g0 * zi.x + (1.f - g0) * zj.x,
                                           g1 * zi.y + (1.f - g1) * zj.y);
                    *(float2*)&C[base] = o;
                }
            }
        }
    }
}

// ---------------- MMA attention (round-8, unchanged — 3xTF32) ----------------
#define KV_LD 36    // uint2 stride
#define P_LD 40     // f32 stride
#define ATTN_SMEM (224*KV_LD*8*2 + 8*32*P_LD*4*2)   // 210944 B

__global__ __launch_bounds__(256)
void attn_mma(const float* __restrict__ Q, const float* __restrict__ K,
              const float* __restrict__ V,
              float* __restrict__ Zi, float* __restrict__ Zj)
{
    extern __shared__ char smraw[];
    uint2* Ks = (uint2*)smraw;               // [224][36]
    uint2* Vs = Ks + 224 * KV_LD;            // [224][36]
    float* Pw  = (float*)(Vs + 224 * KV_LD); // [8][32*40]
    float* Piw = Pw + 8 * 32 * P_LD;         // [8][32*40]

    const int bt = blockIdx.x >> 3;
    const int h  = blockIdx.x & 7;
    const size_t base = ((size_t)bt * NNODE) * DMODEL + h * DHEAD;
    const int tid = threadIdx.x;
    const int w = tid >> 5, lane = tid & 31;
    const int g = lane >> 2, tig = lane & 3;

    for (int idx = tid; idx < 224 * 32; idx += 256) {
        int row = idx >> 5, col = idx & 31;
        float kv = 0.f, vv = 0.f;
        if (row < NNODE) {
            kv = K[base + (size_t)row * DMODEL + col];
            vv = V[base + (size_t)row * DMODEL + col];
        }
        Ks[row * KV_LD + col] = split2(kv);
        Vs[row * KV_LD + col] = split2(vv);
    }

    float* myP  = Pw  + w * (32 * P_LD);
    float* myPi = Piw + w * (32 * P_LD);
    for (int i = lane; i < 32 * P_LD; i += 32) myPi[i] = 0.f;

    const float scale = 0.1767766952966369f; // 1/sqrt(32)
    unsigned qh[2][4][4], ql[2][4][4];
#pragma unroll
    for (int mt = 0; mt < 2; mt++)
#pragma unroll
        for (int ks = 0; ks < 4; ks++) {
            int r0 = mt * 16 + g, r1 = r0 + 8;
            int n0 = w + 8 * r0; if (n0 > 206) n0 = 206;
            int n1 = w + 8 * r1; if (n1 > 206) n1 = 206;
            int k0 = 8 * ks + tig;
            float a0 = Q[base + (size_t)n0 * DMODEL + k0] * scale;
            float a1 = Q[base + (size_t)n1 * DMODEL + k0] * scale;
            float a2 = Q[base + (size_t)n0 * DMODEL + k0 + 4] * scale;
            float a3 = Q[base + (size_t)n1 * DMODEL + k0 + 4] * scale;
            uint2 s0 = split2(a0), s1 = split2(a1), s2 = split2(a2), s3 = split2(a3);
            qh[mt][ks][0] = s0.x; ql[mt][ks][0] = s0.y;
            qh[mt][ks][1] = s1.x; ql[mt][ks][1] = s1.y;
            qh[mt][ks][2] = s2.x; ql[mt][ks][2] = s2.y;
            qh[mt][ks][3] = s3.x; ql[mt][ks][3] = s3.y;
        }
    __syncthreads();

    float4 zall[2][4], zint[2][4];
#pragma unroll
    for (int mt = 0; mt < 2; mt++)
#pragma unroll
        for (int nt = 0; nt < 4; nt++) {
            zall[mt][nt] = make_float4(0.f, 0.f, 0.f, 0.f);
            zint[mt][nt] = make_float4(0.f, 0.f, 0.f, 0.f);
        }
    float sa[4] = {0.f, 0.f, 0.f, 0.f};
    float si[4] = {0.f, 0.f, 0.f, 0.f};
    const bool isHolder = (tig == (w >> 1));
    const int wodd = w & 1;

    for (int ct = 0; ct < 7; ct++) {
        const int mbase = 32 * ct;

        float4 sacc[2][4];
#pragma unroll
        for (int mt = 0; mt < 2; mt++)
#pragma unroll
            for (int nt = 0; nt < 4; nt++) sacc[mt][nt] = make_float4(0.f, 0.f, 0.f, 0.f);

#pragma unroll
        for (int ks = 0; ks < 4; ks++)
#pragma unroll
            for (int nt = 0; nt < 4; nt++) {
                int mrow = (mbase + 8 * nt + g) * KV_LD;
                uint2 kb0 = Ks[mrow + 8 * ks + tig];
                uint2 kb1 = Ks[mrow + 8 * ks + tig + 4];
                unsigned bh[2] = {kb0.x, kb1.x};
                unsigned bl[2] = {kb0.y, kb1.y};
#pragma unroll
                for (int mt = 0; mt < 2; mt++) {
                    mma_tf32(sacc[mt][nt], qh[mt][ks], bh);
                    mma_tf32(sacc[mt][nt], qh[mt][ks], bl);
                    mma_tf32(sacc[mt][nt], ql[mt][ks], bh);
                }
            }

#pragma unroll
        for (int mt = 0; mt < 2; mt++)
#pragma unroll
            for (int nt = 0; nt < 4; nt++) {
                float4 c = sacc[mt][nt];
                int m0 = mbase + 8 * nt + 2 * tig, m1 = m0 + 1;
                int r0 = mt * 16 + g, r1 = r0 + 8;
                int n0 = w + 8 * r0, n1 = w + 8 * r1;
                c.x = (m0 <= 206 && m0 != n0) ? __expf(c.x) : 0.f;
                c.y = (m1 <= 206 && m1 != n0) ? __expf(c.y) : 0.f;
                c.z = (m0 <= 206 && m0 != n1) ? __expf(c.z) : 0.f;
                c.w = (m1 <= 206 && m1 != n1) ? __expf(c.w) : 0.f;
                sa[mt * 2 + 0] += c.x + c.y;
                sa[mt * 2 + 1] += c.z + c.w;
                if (isHolder) {
                    float v0 = wodd ? c.y : c.x;
                    float v1 = wodd ? c.w : c.z;
                    si[mt * 2 + 0] += v0;
                    si[mt * 2 + 1] += v1;
                    myPi[r0 * P_LD + 4 * ct + nt] = v0;
                    myPi[r1 * P_LD + 4 * ct + nt] = v1;
                }
                *(float2*)&myP[r0 * P_LD + 8 * nt + 2 * tig] = make_float2(c.x, c.y);
                *(float2*)&myP[r1 * P_LD + 8 * nt + 2 * tig] = make_float2(c.z, c.w);
            }
        __syncwarp();

#pragma unroll
        for (int ks = 0; ks < 4; ks++) {
            unsigned ah[2][4], al[2][4];
#pragma unroll
            for (int mt = 0; mt < 2; mt++) {
                int r0 = (mt * 16 + g) * P_LD, r1 = (mt * 16 + g + 8) * P_LD;
                float p0 = myP[r0 + 8 * ks + tig];
                float p1 = myP[r1 + 8 * ks + tig];
                float p2 = myP[r0 + 8 * ks + tig + 4];
                float p3 = myP[r1 + 8 * ks + tig + 4];
                uint2 s0 = split2(p0), s1 = split2(p1), s2 = split2(p2), s3 = split2(p3);
                ah[mt][0] = s0.x; al[mt][0] = s0.y;
                ah[mt][1] = s1.x; al[mt][1] = s1.y;
                ah[mt][2] = s2.x; al[mt][2] = s2.y;
                ah[mt][3] = s3.x; al[mt][3] = s3.y;
            }
#pragma unroll
            for (int nt = 0; nt < 4; nt++) {
                int kr = mbase + 8 * ks + tig;
                uint2 vb0 = Vs[kr * KV_LD + 8 * nt + g];
                uint2 vb1 = Vs[(kr + 4) * KV_LD + 8 * nt + g];
                unsigned bh[2] = {vb0.x, vb1.x};
                unsigned bl[2] = {vb0.y, vb1.y};
#pragma unroll
                for (int mt = 0; mt < 2; mt++) {
                    mma_tf32(zall[mt][nt], ah[mt], bh);
                    mma_tf32(zall[mt][nt], ah[mt], bl);
                    mma_tf32(zall[mt][nt], al[mt], bh);
                }
            }
        }
        __syncwarp();
    }

#pragma unroll
    for (int ks = 0; ks < 4; ks++) {
        unsigned ah[2][4], al[2][4];
#pragma unroll
        for (int mt = 0; mt < 2; mt++) {
            int r0 = (mt * 16 + g) * P_LD, r1 = (mt * 16 + g + 8) * P_LD;
            float p0 = myPi[r0 + 8 * ks + tig];
            float p1 = myPi[r1 + 8 * ks + tig];
            float p2 = myPi[r0 + 8 * ks + tig + 4];
            float p3 = myPi[r1 + 8 * ks + tig + 4];
            uint2 s0 = split2(p0), s1 = split2(p1), s2 = split2(p2), s3 = split2(p3);
            ah[mt][0] = s0.x; al[mt][0] = s0.y;
            ah[mt][1] = s1.x; al[mt][1] = s1.y;
            ah[mt][2] = s2.x; al[mt][2] = s2.y;
            ah[mt][3] = s3.x; al[mt][3] = s3.y;
        }
#pragma unroll
        for (int nt = 0; nt < 4; nt++) {
            int k0 = 8 * ks + tig;
            int mk0 = w + 8 * k0;       if (mk0 > 223) mk0 = 223;
            int mk1 = w + 8 * (k0 + 4); if (mk1 > 223) mk1 = 223;
            uint2 vb0 = Vs[mk0 * KV_LD + 8 * nt + g];
            uint2 vb1 = Vs[mk1 * KV_LD + 8 * nt + g];
            unsigned bh[2] = {vb0.x, vb1.x};
            unsigned bl[2] = {vb0.y, vb1.y};
#pragma unroll
            for (int mt = 0; mt < 2; mt++) {
                mma_tf32(zint[mt][nt], ah[mt], bh);
                mma_tf32(zint[mt][nt], ah[mt], bl);
                mma_tf32(zint[mt][nt], al[mt], bh);
            }
        }
    }

    float ri[4], rj[4];
#pragma unroll
    for (int i = 0; i < 4; i++) {
        float a = sa[i], s = si[i];
        a += __shfl_xor_sync(0xffffffffu, a, 1);
        a += __shfl_xor_sync(0xffffffffu, a, 2);
        s += __shfl_xor_sync(0xffffffffu, s, 1);
        s += __shfl_xor_sync(0xffffffffu, s, 2);
        ri[i] = 1.f / s;
        rj[i] = 1.f / (a - s);
    }

    __syncwarp();
#pragma unroll
    for (int mt = 0; mt < 2; mt++)
#pragma unroll
        for (int nt = 0; nt < 4; nt++) {
            int r0 = mt * 16 + g, r1 = r0 + 8;
            float4 za = zall[mt][nt], zi4 = zint[mt][nt];
            float ri0 = ri[mt * 2], ri1 = ri[mt * 2 + 1];
            float rj0 = rj[mt * 2], rj1 = rj[mt * 2 + 1];
            *(float2*)&myP [r0 * P_LD + 8 * nt + 2 * tig] = make_float2(zi4.x * ri0, zi4.y * ri0);
            *(float2*)&myP [r1 * P_LD + 8 * nt + 2 * tig] = make_float2(zi4.z * ri1, zi4.w * ri1);
            *(float2*)&myPi[r0 * P_LD + 8 * nt + 2 * tig] = make_float2((za.x - zi4.x) * rj0, (za.y - zi4.y) * rj0);
            *(float2*)&myPi[r1 * P_LD + 8 * nt + 2 * tig] = make_float2((za.z - zi4.z) * rj1, (za.w - zi4.w) * rj1);
        }
    __syncwarp();
#pragma unroll 4
    for (int rr = 0; rr < 32; rr++) {
        int n = w + 8 * rr;
        if (n < NNODE) {
            Zi[base + (size_t)n * DMODEL + lane] = myP [rr * P_LD + lane];
            Zj[base + (size_t)n * DMODEL + lane] = myPi[rr * P_LD + lane];
        }
    }
}

// ---------------- launch --------------------------------------------------
extern "C" void kernel_launch(void* const* d_in, const int* in_sizes, int n_in,
                              void* d_out, int out_size)
{
    const float* x  = (const float*)d_in[0];
    const float* Wq = (const float*)d_in[1];
    const float* bq = (const float*)d_in[2];
    const float* Wk = (const float*)d_in[3];
    const float* bk = (const float*)d_in[4];
    const float* Wv = (const float*)d_in[5];
    const float* bv = (const float*)d_in[6];
    const float* Wg = (const float*)d_in[7];
    const float* bg = (const float*)d_in[8];
    const float* Wp = (const float*)d_in[9];
    const float* bp = (const float*)d_in[10];
    float* out = (float*)d_out;

    float *Q, *Kp, *Vp, *Zi, *Zj, *Zc;
    uint2 *W2;
    cudaGetSymbolAddress((void**)&Q,  g_Q);
    cudaGetSymbolAddress((void**)&Kp, g_K);
    cudaGetSymbolAddress((void**)&Vp, g_V);
    cudaGetSymbolAddress((void**)&Zi, g_Zi);
    cudaGetSymbolAddress((void**)&Zj, g_Zj);
    cudaGetSymbolAddress((void**)&Zc, g_Zc);
    cudaGetSymbolAddress((void**)&W2, g_W2);

    cudaFuncSetAttribute(gemm_tc<0>, cudaFuncAttributeMaxDynamicSharedMemorySize, GEMM_SMEM);
    cudaFuncSetAttribute(gemm_tc<1>, cudaFuncAttributeMaxDynamicSharedMemorySize, GEMM_SMEM);
    cudaFuncSetAttribute(gemm_tc<2>, cudaFuncAttributeMaxDynamicSharedMemorySize, GEMM_SMEM);
    cudaFuncSetAttribute(attn_mma,   cudaFuncAttributeMaxDynamicSharedMemorySize, ATTN_SMEM);

    const int mblocks = (MTOT + GBM - 1) / GBM;   // 311

    split_weights<<<(WP_TOTAL + 255) / 256, 256>>>(Wq, Wk, Wv, Wp, Wg);

    gemm_tc<2><<<dim3(mblocks, 6), 256, GEMM_SMEM>>>(
        x, nullptr, W2 + OFFP_WQ, bq, bk, bv,
        nullptr, nullptr, Q, Kp, Vp, MTOT, DMODEL);

    attn_mma<<<BTT * NHEADS, 256, ATTN_SMEM>>>(Q, Kp, Vp, Zi, Zj);

    gemm_tc<1><<<dim3(mblocks, 2), 256, GEMM_SMEM>>>(
        Zi, Zj, W2 + OFFP_WG, bg, nullptr, nullptr,
        Zi, Zj, Zc, nullptr, nullptr, MTOT, 2 * DMODEL);

    gemm_tc<0><<<dim3(mblocks, 2), 256, GEMM_SMEM>>>(
        Zc, nullptr, W2 + OFFP_WP, bp, nullptr, nullptr,
        nullptr, nullptr, out, nullptr, nullptr, MTOT, DMODEL);
}